// round 2
// baseline (speedup 1.0000x reference)
#include <cuda_runtime.h>
#include <cuda_bf16.h>
#include <cstdint>

#define BB 8
#define NN 4096
#define KK 10
#define BNPTS (BB*NN)          // 32768
#define EDGE_COUNT 327680.0f   // B*N*K
#define TAU 0.2f
#define EPS 1e-5f
#define FULLMASK 0xffffffffu

// ---------------- device scratch (no allocations allowed) ----------------
__device__ int   d_nbr[BNPTS*11];
__device__ float d_buf1[BNPTS*128];     // u1(64)|v1(64)
__device__ float d_m1[BNPTS*64];        // max_k z (stage1)
__device__ float d_f1[BNPTS*64];
__device__ float d_buf2[BNPTS*384];     // u2(128)|v2(128)|us2(64)|vs2(64)
__device__ float d_f2[BNPTS*128];
__device__ float d_buf3[BNPTS*768];     // u3(256)|v3(256)|us3(128)|vs3(128)
__device__ float d_f3[BNPTS*256];
__device__ float d_hall[BNPTS*64];
__device__ float d_Wcat2[64*384];
__device__ float d_Wcat3[128*768];
__device__ float d_stats[512];          // sum[0..255], sumsq[256..511]
__device__ float d_scale[256];
__device__ float d_shift[256];
__device__ float d_wlog[BNPTS];
__device__ float d_bmax[BB];
__device__ float d_bsum[BB];
__device__ float d_pooled[BB*256];

// ---------------- KNN: warp-per-query brute force ----------------
// block: 128 threads (4 warps), each warp does 4 queries sequentially.
// dyn smem: float4 cand[4096] (64KB) + merge buf 4*352 u64 (11KB)
#define KNN_SMEM (4096*16 + 4*32*11*8)

__global__ void knn_kernel(const float* __restrict__ x, int* __restrict__ nbr)
{
    extern __shared__ unsigned char smem_raw[];
    float4* cand = (float4*)smem_raw;
    unsigned long long* mb = (unsigned long long*)(cand + 4096);

    const int b    = blockIdx.y;
    const int tid  = threadIdx.x;
    const int warp = tid >> 5;
    const int lane = tid & 31;

    for (int i = tid; i < 4096; i += blockDim.x) {
        const float* xp = x + ((size_t)b*4096 + i)*5;
        float cx = xp[0], cy = xp[1], cz = xp[2];
        cand[i] = make_float4(cx, cy, cz, cx*cx + cy*cy + cz*cz);
    }
    __syncthreads();

    for (int qi = 0; qi < 4; qi++) {
        const int q = blockIdx.x*16 + warp*4 + qi;
        const float4 Q = cand[q];

        float ad[11]; int ai[11];
        #pragma unroll
        for (int p = 0; p < 11; p++) { ad[p] = 3.4e38f; ai[p] = 0x7fffffff; }

        for (int m = lane; m < 4096; m += 32) {
            float4 c = cand[m];
            // key = d2 - |q|^2 (constant per query; ordering preserved)
            float key = c.w - 2.f*(Q.x*c.x + Q.y*c.y + Q.z*c.z);
            if (key < ad[10]) {
                ad[10] = key; ai[10] = m;
                #pragma unroll
                for (int p = 10; p > 0; --p) {
                    if (ad[p] < ad[p-1]) {
                        float tf = ad[p]; ad[p] = ad[p-1]; ad[p-1] = tf;
                        int   ti = ai[p]; ai[p] = ai[p-1]; ai[p-1] = ti;
                    }
                }
            }
        }
        // write per-lane sorted lists to smem as orderable u64 keys
        unsigned long long* my = mb + warp*352 + lane*11;
        #pragma unroll
        for (int p = 0; p < 11; p++) {
            unsigned int u = __float_as_uint(ad[p]);
            u = (u & 0x80000000u) ? ~u : (u | 0x80000000u);
            my[p] = ((unsigned long long)u << 32) | (unsigned int)ai[p];
        }
        __syncwarp();
        // merge: 11 rounds of warp-min over list heads
        unsigned long long* base = mb + warp*352;
        int ptr = 0;
        for (int r = 0; r < 11; r++) {
            unsigned long long h = base[lane*11 + ptr];
            unsigned long long mn = h;
            #pragma unroll
            for (int off = 16; off; off >>= 1) {
                unsigned long long o = __shfl_xor_sync(FULLMASK, mn, off);
                if (o < mn) mn = o;
            }
            if (h == mn) ptr++;
            if (lane == 0)
                nbr[((size_t)b*4096 + q)*11 + r] = b*4096 + (int)(mn & 0xffffffffu);
        }
        __syncwarp();
    }
}

// ---------------- weight prep: concat split matrices ----------------
__global__ void prep_kernel(const float* __restrict__ W2, const float* __restrict__ Ws2a,
                            const float* __restrict__ W3, const float* __restrict__ Ws3a,
                            float* __restrict__ Wc2, float* __restrict__ Wc3)
{
    int i = blockIdx.x*blockDim.x + threadIdx.x;
    if (i < 64*384) {
        int r = i/384, c = i%384;
        float v;
        if      (c < 128) v = W2[r*128 + c];
        else if (c < 256) v = W2[(64+r)*128 + (c-128)];
        else if (c < 320) v = Ws2a[r*64 + (c-256)];
        else              v = Ws2a[(64+r)*64 + (c-320)];
        Wc2[i] = v;
    } else {
        int j = i - 64*384;
        if (j < 128*768) {
            int r = j/768, c = j%768;
            float v;
            if      (c < 256) v = W3[r*256 + c];
            else if (c < 512) v = W3[(128+r)*256 + (c-256)];
            else if (c < 640) v = Ws3a[r*128 + (c-512)];
            else              v = Ws3a[(128+r)*128 + (c-640)];
            Wc3[j] = v;
        }
    }
}

// ---------------- stage-1 u/v (5-dim input, tiny) ----------------
__global__ void uv1_kernel(const float* __restrict__ x, const float* __restrict__ W1,
                           float* __restrict__ buf1)
{
    int idx = blockIdx.x*blockDim.x + threadIdx.x;
    if (idx >= BNPTS*64) return;
    int n = idx >> 6, c = idx & 63;
    const float* xp = x + (size_t)n*5;
    float x0 = xp[0], x1 = xp[1], x2 = xp[2], x3 = xp[3], x4 = xp[4];
    float u = x0*W1[0*64+c] + x1*W1[1*64+c] + x2*W1[2*64+c] + x3*W1[6*64+c] + x4*W1[7*64+c];
    float v = x0*W1[3*64+c] + x1*W1[4*64+c] + x2*W1[5*64+c] + x3*W1[8*64+c] + x4*W1[9*64+c];
    buf1[n*128 + c]      = u;
    buf1[n*128 + 64 + c] = v;
}

// ---------------- generic zero ----------------
__global__ void zero_kernel(float* __restrict__ p, int n)
{
    int i = blockIdx.x*blockDim.x + threadIdx.x;
    if (i < n) p[i] = 0.f;
}

// ---------------- BN statistics over edges (blockDim.x == C) ----------------
__global__ void stats_kernel(const float* __restrict__ buf, int stride, int uoff, int voff,
                             const int* __restrict__ nbr, int koff, int ppb,
                             float* __restrict__ stats, float* __restrict__ maxOut)
{
    const int c = threadIdx.x;
    const int C = blockDim.x;
    const int p0 = blockIdx.x * ppb;
    float sum = 0.f, ss = 0.f;
    for (int p = 0; p < ppb; p++) {
        int n = p0 + p;
        float un = buf[(size_t)n*stride + uoff + c];
        float vn = buf[(size_t)n*stride + voff + c];
        float w = vn - un;
        float mx = -3.4e38f;
        #pragma unroll
        for (int k = 0; k < KK; k++) {
            int j = nbr[n*11 + koff + k];
            float z = buf[(size_t)j*stride + uoff + c] + w;
            sum += z; ss += z*z;
            mx = fmaxf(mx, z);
        }
        if (maxOut) maxOut[(size_t)n*C + c] = mx;
    }
    atomicAdd(&stats[c], sum);
    atomicAdd(&stats[256 + c], ss);
}

__global__ void finalize_kernel(const float* __restrict__ stats,
                                const float* __restrict__ g, const float* __restrict__ bb,
                                int C, float cnt,
                                float* __restrict__ scale, float* __restrict__ shift)
{
    int c = blockIdx.x*blockDim.x + threadIdx.x;
    if (c >= C) return;
    float mean = stats[c] / cnt;
    float var  = stats[256 + c] / cnt - mean*mean;
    float rs = rsqrtf(var + EPS);
    float sc = g[c]*rs;
    scale[c] = sc;
    shift[c] = bb[c] - mean*sc;
}

// ---------------- f1 = relu(scale*max_k z + shift) ----------------
__global__ void f1_kernel(const float* __restrict__ m1, const float* __restrict__ scale,
                          const float* __restrict__ shift, float* __restrict__ f1)
{
    int idx = blockIdx.x*blockDim.x + threadIdx.x;
    if (idx >= BNPTS*64) return;
    int c = idx & 63;
    f1[idx] = fmaxf(scale[c]*m1[idx] + shift[c], 0.f);
}

// ---------------- generic fp32 tiled GEMM: C = A(MxK) @ B(KxN) ----------------
template<int BM, int BN, int TM, int TN, int NT>
__global__ __launch_bounds__(NT) void gemm_kernel(
    const float* __restrict__ A, const float* __restrict__ B, float* __restrict__ C,
    int M, int N, int Kd)
{
    __shared__ float As[16][BM + 4];
    __shared__ float Bs[16][BN];
    const int tid = threadIdx.x;
    constexpr int TX = BN / TN;
    const int tx = tid % TX;
    const int ty = tid / TX;
    const int rowBase = blockIdx.x * BM;
    const int colBase = blockIdx.y * BN;

    float acc[TM][TN];
    #pragma unroll
    for (int i = 0; i < TM; i++)
        #pragma unroll
        for (int j = 0; j < TN; j++) acc[i][j] = 0.f;

    for (int k0 = 0; k0 < Kd; k0 += 16) {
        #pragma unroll 2
        for (int i = tid; i < BM*4; i += NT) {          // BM*16/4 float4 loads
            int r = i >> 2, kk = (i & 3) * 4;
            const float4 v = *reinterpret_cast<const float4*>(
                &A[(size_t)(rowBase + r)*Kd + k0 + kk]);
            As[kk+0][r] = v.x; As[kk+1][r] = v.y; As[kk+2][r] = v.z; As[kk+3][r] = v.w;
        }
        #pragma unroll 2
        for (int i = tid; i < BN*4; i += NT) {          // 16*BN/4 float4 loads
            int kk = i / (BN/4), c4 = (i % (BN/4)) * 4;
            *reinterpret_cast<float4*>(&Bs[kk][c4]) =
                *reinterpret_cast<const float4*>(&B[(size_t)(k0 + kk)*N + colBase + c4]);
        }
        __syncthreads();
        #pragma unroll
        for (int kk = 0; kk < 16; kk++) {
            float a[TM], bv[TN];
            #pragma unroll
            for (int i = 0; i < TM; i += 4) {
                float4 v = *reinterpret_cast<const float4*>(&As[kk][ty*TM + i]);
                a[i] = v.x; a[i+1] = v.y; a[i+2] = v.z; a[i+3] = v.w;
            }
            #pragma unroll
            for (int j = 0; j < TN; j += 4) {
                float4 v = *reinterpret_cast<const float4*>(&Bs[kk][tx*TN + j]);
                bv[j] = v.x; bv[j+1] = v.y; bv[j+2] = v.z; bv[j+3] = v.w;
            }
            #pragma unroll
            for (int i = 0; i < TM; i++)
                #pragma unroll
                for (int j = 0; j < TN; j++)
                    acc[i][j] = fmaf(a[i], bv[j], acc[i][j]);
        }
        __syncthreads();
    }
    #pragma unroll
    for (int i = 0; i < TM; i++) {
        float* cp = &C[(size_t)(rowBase + ty*TM + i)*N + colBase + tx*TN];
        #pragma unroll
        for (int j = 0; j < TN; j++) cp[j] = acc[i][j];
    }
}

// ---------------- soft-edge aggregation (block per point, blockDim.x == C) -------
template<int C, int CA>
__global__ void softedge_kernel(const float* __restrict__ buf, const int* __restrict__ nbr,
                                const float* __restrict__ scale, const float* __restrict__ shift,
                                const float* __restrict__ ab,   // attention bias (CA)
                                const float* __restrict__ Wb, const float* __restrict__ bb,
                                float* __restrict__ fout)
{
    constexpr int STRIDE = 2*C + 2*CA;
    constexpr int AOFF = 2*C;
    const int n = blockIdx.x;
    const int t = threadIdx.x;

    __shared__ int   js[KK];
    __shared__ float wps[KK][C/32];
    __shared__ float alpha[KK];

    if (t < KK) js[t] = nbr[n*11 + 1 + t];
    __syncthreads();

    // attention logits
    float base_a = 0.f, usn = 0.f;
    if (t < CA) {
        usn = buf[(size_t)n*STRIDE + AOFF + t];
        base_a = buf[(size_t)n*STRIDE + AOFF + CA + t] - usn + ab[t];
    }
    #pragma unroll
    for (int k = 0; k < KK; k++) {
        float v = 0.f;
        if (t < CA) {
            float h = buf[(size_t)js[k]*STRIDE + AOFF + t] + base_a;
            h = fmaxf(h, 0.f);
            v = h * Wb[t];
        }
        #pragma unroll
        for (int off = 16; off; off >>= 1) v += __shfl_down_sync(FULLMASK, v, off);
        if ((t & 31) == 0) wps[k][t >> 5] = v;
    }
    __syncthreads();
    if (t < KK) {
        float s = 0.f;
        #pragma unroll
        for (int w = 0; w < C/32; w++) s += wps[t][w];
        alpha[t] = (s + bb[0]) / TAU;
    }
    __syncthreads();
    if (t == 0) {
        float mx = -3.4e38f;
        #pragma unroll
        for (int k = 0; k < KK; k++) mx = fmaxf(mx, alpha[k]);
        float s = 0.f;
        #pragma unroll
        for (int k = 0; k < KK; k++) { float e = expf(alpha[k] - mx); alpha[k] = e; s += e; }
        float inv = 1.f / s;
        #pragma unroll
        for (int k = 0; k < KK; k++) alpha[k] *= inv;
    }
    __syncthreads();

    // weighted sum of relu(bn(z))
    float un = buf[(size_t)n*STRIDE + t];
    float w  = buf[(size_t)n*STRIDE + C + t] - un;
    float sc = scale[t], sh = shift[t];
    float acc = 0.f;
    #pragma unroll
    for (int k = 0; k < KK; k++) {
        float z = buf[(size_t)js[k]*STRIDE + t] + w;
        acc += alpha[k] * fmaxf(sc*z + sh, 0.f);
    }
    fout[(size_t)n*C + t] = acc;
}

// ---------------- final attention pooling ----------------
__global__ void wlog_kernel(const float* __restrict__ hall, const float* __restrict__ ba1,
                            const float* __restrict__ Wa2, const float* __restrict__ ba2,
                            float* __restrict__ wlog)
{
    int gw = (blockIdx.x*blockDim.x + threadIdx.x) >> 5;
    int lane = threadIdx.x & 31;
    if (gw >= BNPTS) return;
    float acc = 0.f;
    #pragma unroll
    for (int h = 0; h < 2; h++) {
        int c = lane + 32*h;
        float v = fmaxf(hall[(size_t)gw*64 + c] + ba1[c], 0.f);
        acc += v * Wa2[c];
    }
    #pragma unroll
    for (int off = 16; off; off >>= 1) acc += __shfl_down_sync(FULLMASK, acc, off);
    if (lane == 0) wlog[gw] = acc + ba2[0];
}

__global__ void batred_kernel(const float* __restrict__ wlog, float* __restrict__ bmax,
                              float* __restrict__ bsum)
{
    int b = blockIdx.x, t = threadIdx.x;
    __shared__ float red[256];
    float mx = -3.4e38f;
    for (int n = t; n < NN; n += 256) mx = fmaxf(mx, wlog[b*NN + n]);
    red[t] = mx; __syncthreads();
    for (int s = 128; s; s >>= 1) { if (t < s) red[t] = fmaxf(red[t], red[t+s]); __syncthreads(); }
    float M = red[0]; __syncthreads();
    float s = 0.f;
    for (int n = t; n < NN; n += 256) s += expf(wlog[b*NN + n] - M);
    red[t] = s; __syncthreads();
    for (int st = 128; st; st >>= 1) { if (t < st) red[t] += red[t+st]; __syncthreads(); }
    if (t == 0) { bmax[b] = M; bsum[b] = red[0]; }
}

__global__ void pool_kernel(const float* __restrict__ f3, const float* __restrict__ wlog,
                            const float* __restrict__ bmax, const float* __restrict__ bsum,
                            float* __restrict__ pooled)
{
    int b = blockIdx.y, t = threadIdx.x;
    int n0 = blockIdx.x * 256;
    __shared__ float ew[256];
    ew[t] = expf(wlog[b*NN + n0 + t] - bmax[b]) / bsum[b];
    __syncthreads();
    float acc = 0.f;
    for (int i = 0; i < 256; i++)
        acc += ew[i] * f3[((size_t)b*NN + n0 + i)*256 + t];
    atomicAdd(&pooled[b*256 + t], acc);
}

__global__ void final_kernel(const float* __restrict__ pooled, const float* __restrict__ Wfc,
                             const float* __restrict__ bfc, float* __restrict__ out)
{
    int b = blockIdx.x, t = threadIdx.x;
    __shared__ float p[256];
    p[t] = pooled[b*256 + t];
    __syncthreads();
    float acc = bfc[t];
    for (int i = 0; i < 256; i++) acc = fmaf(p[i], Wfc[i*256 + t], acc);
    out[b*256 + t] = fmaxf(acc, 0.f);
}

// ---------------- host launcher ----------------
static void* sym_addr_helper(const void* symbol)
{
    void* p = nullptr;
    cudaGetSymbolAddress(&p, symbol);
    return p;
}

extern "C" void kernel_launch(void* const* d_in, const int* in_sizes, int n_in,
                              void* d_out, int out_size)
{
    const float* x    = (const float*)d_in[0];
    const float* W1   = (const float*)d_in[1];
    const float* g1   = (const float*)d_in[2];
    const float* b1   = (const float*)d_in[3];
    const float* W2   = (const float*)d_in[4];
    const float* g2   = (const float*)d_in[5];
    const float* b2   = (const float*)d_in[6];
    const float* Ws2a = (const float*)d_in[7];
    const float* bs2a = (const float*)d_in[8];
    const float* Ws2b = (const float*)d_in[9];
    const float* bs2b = (const float*)d_in[10];
    const float* W3   = (const float*)d_in[11];
    const float* g3   = (const float*)d_in[12];
    const float* b3   = (const float*)d_in[13];
    const float* Ws3a = (const float*)d_in[14];
    const float* bs3a = (const float*)d_in[15];
    const float* Ws3b = (const float*)d_in[16];
    const float* bs3b = (const float*)d_in[17];
    const float* Wa1  = (const float*)d_in[18];
    const float* ba1  = (const float*)d_in[19];
    const float* Wa2  = (const float*)d_in[20];
    const float* ba2  = (const float*)d_in[21];
    const float* Wfc  = (const float*)d_in[22];
    const float* bfc  = (const float*)d_in[23];
    float* out = (float*)d_out;
    (void)in_sizes; (void)n_in; (void)out_size;

    int*   nbr    = (int*)  sym_addr_helper(d_nbr);
    float* buf1   = (float*)sym_addr_helper(d_buf1);
    float* m1     = (float*)sym_addr_helper(d_m1);
    float* f1     = (float*)sym_addr_helper(d_f1);
    float* buf2   = (float*)sym_addr_helper(d_buf2);
    float* f2     = (float*)sym_addr_helper(d_f2);
    float* buf3   = (float*)sym_addr_helper(d_buf3);
    float* f3     = (float*)sym_addr_helper(d_f3);
    float* hall   = (float*)sym_addr_helper(d_hall);
    float* Wc2    = (float*)sym_addr_helper(d_Wcat2);
    float* Wc3    = (float*)sym_addr_helper(d_Wcat3);
    float* stats  = (float*)sym_addr_helper(d_stats);
    float* scale  = (float*)sym_addr_helper(d_scale);
    float* shift  = (float*)sym_addr_helper(d_shift);
    float* wlog   = (float*)sym_addr_helper(d_wlog);
    float* bmax   = (float*)sym_addr_helper(d_bmax);
    float* bsum   = (float*)sym_addr_helper(d_bsum);
    float* pooled = (float*)sym_addr_helper(d_pooled);

    cudaFuncSetAttribute(knn_kernel, cudaFuncAttributeMaxDynamicSharedMemorySize, KNN_SMEM);

    // 1) KNN (top-11 incl. self per point)
    knn_kernel<<<dim3(256, BB), 128, KNN_SMEM>>>(x, nbr);

    // 2) weight concat prep
    prep_kernel<<<(64*384 + 128*768 + 255)/256, 256>>>(W2, Ws2a, W3, Ws3a, Wc2, Wc3);

    // 3) stage 1
    uv1_kernel<<<BNPTS*64/256, 256>>>(x, W1, buf1);
    zero_kernel<<<2, 256>>>(stats, 512);
    stats_kernel<<<BNPTS/16, 64>>>(buf1, 128, 0, 64, nbr, 0, 16, stats, m1);
    finalize_kernel<<<1, 64>>>(stats, g1, b1, 64, EDGE_COUNT, scale, shift);
    f1_kernel<<<BNPTS*64/256, 256>>>(m1, scale, shift, f1);

    // 4) stage 2
    gemm_kernel<128,128,8,8,256><<<dim3(BNPTS/128, 3), 256>>>(f1, Wc2, buf2, BNPTS, 384, 64);
    zero_kernel<<<2, 256>>>(stats, 512);
    stats_kernel<<<BNPTS/16, 128>>>(buf2, 384, 0, 128, nbr, 1, 16, stats, nullptr);
    finalize_kernel<<<1, 128>>>(stats, g2, b2, 128, EDGE_COUNT, scale, shift);
    softedge_kernel<128,64><<<BNPTS, 128>>>(buf2, nbr, scale, shift, bs2a, Ws2b, bs2b, f2);

    // 5) stage 3
    gemm_kernel<128,128,8,8,256><<<dim3(BNPTS/128, 6), 256>>>(f2, Wc3, buf3, BNPTS, 768, 128);
    zero_kernel<<<2, 256>>>(stats, 512);
    stats_kernel<<<BNPTS/8, 256>>>(buf3, 768, 0, 256, nbr, 1, 8, stats, nullptr);
    finalize_kernel<<<1, 256>>>(stats, g3, b3, 256, EDGE_COUNT, scale, shift);
    softedge_kernel<256,128><<<BNPTS, 256>>>(buf3, nbr, scale, shift, bs3a, Ws3b, bs3b, f3);

    // 6) attention pooling + head
    gemm_kernel<128,64,8,4,256><<<dim3(BNPTS/128, 1), 256>>>(f3, Wa1, hall, BNPTS, 64, 256);
    wlog_kernel<<<BNPTS/8, 256>>>(hall, ba1, Wa2, ba2, wlog);
    batred_kernel<<<BB, 256>>>(wlog, bmax, bsum);
    zero_kernel<<<BB, 256>>>(pooled, BB*256);
    pool_kernel<<<dim3(NN/256, BB), 256>>>(f3, wlog, bmax, bsum, pooled);
    final_kernel<<<BB, 256>>>(pooled, Wfc, bfc, out);
}

// round 3
// speedup vs baseline: 1.0957x; 1.0957x over previous
#include <cuda_runtime.h>
#include <cuda_bf16.h>
#include <cstdint>

#define BB 8
#define NN 4096
#define KK 10
#define BNPTS (BB*NN)          // 32768
#define EDGE_COUNT 327680.0f   // B*N*K
#define TAU 0.2f
#define EPS 1e-5f
#define FULLMASK 0xffffffffu

// ---------------- device scratch (no allocations allowed) ----------------
__device__ int   d_nbr[BNPTS*11];
__device__ float d_buf1[BNPTS*128];     // u1(64)|v1(64)
__device__ float d_m1[BNPTS*64];        // max_k z (stage1)
__device__ float d_f1[BNPTS*64];
__device__ float d_buf2[BNPTS*384];     // u2(128)|v2(128)|us2(64)|vs2(64)
__device__ float d_f2[BNPTS*128];
__device__ float d_buf3[BNPTS*768];     // u3(256)|v3(256)|us3(128)|vs3(128)
__device__ float d_f3[BNPTS*256];
__device__ float d_hall[BNPTS*64];
__device__ float d_Wcat2[64*384];
__device__ float d_Wcat3[128*768];
__device__ float d_stats[3*512];        // per-stage: sum[0..255], sumsq[256..511]
__device__ float d_scale[3*256];
__device__ float d_shift[3*256];
__device__ float d_wlog[BNPTS];
__device__ float d_bmax[BB];
__device__ float d_bsum[BB];
__device__ float d_pooled[BB*256];

// ---------------- packed f32x2 fma ----------------
__device__ __forceinline__ unsigned long long ffma2(unsigned long long a,
                                                    unsigned long long b,
                                                    unsigned long long c)
{
    unsigned long long d;
    asm("fma.rn.f32x2 %0, %1, %2, %3;" : "=l"(d) : "l"(a), "l"(b), "l"(c));
    return d;
}
__device__ __forceinline__ unsigned long long pack2(float x)
{
    unsigned long long d;
    asm("mov.b64 %0, {%1, %1};" : "=l"(d) : "r"(__float_as_uint(x)));
    return d;
}

// ---------------- zero all accumulators (stats + pooled) ----------------
__global__ void zero_all_kernel(float* __restrict__ stats, float* __restrict__ pooled)
{
    int i = blockIdx.x*blockDim.x + threadIdx.x;
    if (i < 3*512) stats[i] = 0.f;
    if (i < BB*256) pooled[i] = 0.f;
}

// ---------------- KNN: warp-per-query brute force ----------------
#define KNN_SMEM (4096*16 + 4*32*11*8)

__global__ void knn_kernel(const float* __restrict__ x, int* __restrict__ nbr)
{
    extern __shared__ unsigned char smem_raw[];
    float4* cand = (float4*)smem_raw;
    unsigned long long* mb = (unsigned long long*)(cand + 4096);

    const int b    = blockIdx.y;
    const int tid  = threadIdx.x;
    const int warp = tid >> 5;
    const int lane = tid & 31;

    for (int i = tid; i < 4096; i += blockDim.x) {
        const float* xp = x + ((size_t)b*4096 + i)*5;
        float cx = xp[0], cy = xp[1], cz = xp[2];
        cand[i] = make_float4(cx, cy, cz, cx*cx + cy*cy + cz*cz);
    }
    __syncthreads();

    for (int qi = 0; qi < 4; qi++) {
        const int q = blockIdx.x*16 + warp*4 + qi;
        const float4 Q = cand[q];

        float ad[11]; int ai[11];
        #pragma unroll
        for (int p = 0; p < 11; p++) { ad[p] = 3.4e38f; ai[p] = 0x7fffffff; }

        for (int m = lane; m < 4096; m += 32) {
            float4 c = cand[m];
            float key = c.w - 2.f*(Q.x*c.x + Q.y*c.y + Q.z*c.z);
            if (key < ad[10]) {
                ad[10] = key; ai[10] = m;
                #pragma unroll
                for (int p = 10; p > 0; --p) {
                    if (ad[p] < ad[p-1]) {
                        float tf = ad[p]; ad[p] = ad[p-1]; ad[p-1] = tf;
                        int   ti = ai[p]; ai[p] = ai[p-1]; ai[p-1] = ti;
                    }
                }
            }
        }
        unsigned long long* my = mb + warp*352 + lane*11;
        #pragma unroll
        for (int p = 0; p < 11; p++) {
            unsigned int u = __float_as_uint(ad[p]);
            u = (u & 0x80000000u) ? ~u : (u | 0x80000000u);
            my[p] = ((unsigned long long)u << 32) | (unsigned int)ai[p];
        }
        __syncwarp();
        unsigned long long* base = mb + warp*352;
        int ptr = 0;
        for (int r = 0; r < 11; r++) {
            unsigned long long h = base[lane*11 + ptr];
            unsigned long long mn = h;
            #pragma unroll
            for (int off = 16; off; off >>= 1) {
                unsigned long long o = __shfl_xor_sync(FULLMASK, mn, off);
                if (o < mn) mn = o;
            }
            if (h == mn) ptr++;
            if (lane == 0)
                nbr[((size_t)b*4096 + q)*11 + r] = b*4096 + (int)(mn & 0xffffffffu);
        }
        __syncwarp();
    }
}

// ---------------- weight prep: concat split matrices ----------------
__global__ void prep_kernel(const float* __restrict__ W2, const float* __restrict__ Ws2a,
                            const float* __restrict__ W3, const float* __restrict__ Ws3a,
                            float* __restrict__ Wc2, float* __restrict__ Wc3)
{
    int i = blockIdx.x*blockDim.x + threadIdx.x;
    if (i < 64*384) {
        int r = i/384, c = i%384;
        float v;
        if      (c < 128) v = W2[r*128 + c];
        else if (c < 256) v = W2[(64+r)*128 + (c-128)];
        else if (c < 320) v = Ws2a[r*64 + (c-256)];
        else              v = Ws2a[(64+r)*64 + (c-320)];
        Wc2[i] = v;
    } else {
        int j = i - 64*384;
        if (j < 128*768) {
            int r = j/768, c = j%768;
            float v;
            if      (c < 256) v = W3[r*256 + c];
            else if (c < 512) v = W3[(128+r)*256 + (c-256)];
            else if (c < 640) v = Ws3a[r*128 + (c-512)];
            else              v = Ws3a[(128+r)*128 + (c-640)];
            Wc3[j] = v;
        }
    }
}

// ---------------- stage-1 u/v (5-dim input, tiny) ----------------
__global__ void uv1_kernel(const float* __restrict__ x, const float* __restrict__ W1,
                           float* __restrict__ buf1)
{
    int idx = blockIdx.x*blockDim.x + threadIdx.x;
    if (idx >= BNPTS*64) return;
    int n = idx >> 6, c = idx & 63;
    const float* xp = x + (size_t)n*5;
    float x0 = xp[0], x1 = xp[1], x2 = xp[2], x3 = xp[3], x4 = xp[4];
    float u = x0*W1[0*64+c] + x1*W1[1*64+c] + x2*W1[2*64+c] + x3*W1[6*64+c] + x4*W1[7*64+c];
    float v = x0*W1[3*64+c] + x1*W1[4*64+c] + x2*W1[5*64+c] + x3*W1[8*64+c] + x4*W1[9*64+c];
    buf1[n*128 + c]      = u;
    buf1[n*128 + 64 + c] = v;
}

// ---------------- BN statistics over edges (blockDim.x == C) ----------------
__global__ void stats_kernel(const float* __restrict__ buf, int stride, int uoff, int voff,
                             const int* __restrict__ nbr, int koff, int ppb,
                             float* __restrict__ stats, float* __restrict__ maxOut)
{
    const int c = threadIdx.x;
    const int C = blockDim.x;
    const int p0 = blockIdx.x * ppb;
    float sum = 0.f, ss = 0.f;
    for (int p = 0; p < ppb; p++) {
        int n = p0 + p;
        float un = buf[(size_t)n*stride + uoff + c];
        float vn = buf[(size_t)n*stride + voff + c];
        float w = vn - un;
        float mx = -3.4e38f;
        #pragma unroll
        for (int k = 0; k < KK; k++) {
            int j = nbr[n*11 + koff + k];
            float z = buf[(size_t)j*stride + uoff + c] + w;
            sum += z; ss += z*z;
            mx = fmaxf(mx, z);
        }
        if (maxOut) maxOut[(size_t)n*C + c] = mx;
    }
    atomicAdd(&stats[c], sum);
    atomicAdd(&stats[256 + c], ss);
}

__global__ void finalize_kernel(const float* __restrict__ stats,
                                const float* __restrict__ g, const float* __restrict__ bb,
                                int C, float cnt,
                                float* __restrict__ scale, float* __restrict__ shift)
{
    int c = blockIdx.x*blockDim.x + threadIdx.x;
    if (c >= C) return;
    float mean = stats[c] / cnt;
    float var  = stats[256 + c] / cnt - mean*mean;
    float rs = rsqrtf(var + EPS);
    float sc = g[c]*rs;
    scale[c] = sc;
    shift[c] = bb[c] - mean*sc;
}

// ---------------- f1 = relu(scale*max_k z + shift) ----------------
__global__ void f1_kernel(const float* __restrict__ m1, const float* __restrict__ scale,
                          const float* __restrict__ shift, float* __restrict__ f1)
{
    int idx = blockIdx.x*blockDim.x + threadIdx.x;
    if (idx >= BNPTS*64) return;
    int c = idx & 63;
    f1[idx] = fmaxf(scale[c]*m1[idx] + shift[c], 0.f);
}

// ---------------- fp32 tiled GEMM with packed f32x2 accumulate ----------------
// C = A(MxK) @ B(KxN), TN even.
template<int BM, int BN, int TM, int TN, int NT>
__global__ __launch_bounds__(NT) void gemm_kernel(
    const float* __restrict__ A, const float* __restrict__ B, float* __restrict__ C,
    int M, int N, int Kd)
{
    __shared__ __align__(16) float As[16][BM + 4];
    __shared__ __align__(16) float Bs[16][BN];
    const int tid = threadIdx.x;
    constexpr int TX = BN / TN;
    constexpr int TNH = TN / 2;
    const int tx = tid % TX;
    const int ty = tid / TX;
    const int rowBase = blockIdx.x * BM;
    const int colBase = blockIdx.y * BN;

    unsigned long long acc[TM][TNH];
    #pragma unroll
    for (int i = 0; i < TM; i++)
        #pragma unroll
        for (int j = 0; j < TNH; j++) acc[i][j] = 0ull;

    for (int k0 = 0; k0 < Kd; k0 += 16) {
        #pragma unroll 2
        for (int i = tid; i < BM*4; i += NT) {
            int r = i >> 2, kk = (i & 3) * 4;
            const float4 v = *reinterpret_cast<const float4*>(
                &A[(size_t)(rowBase + r)*Kd + k0 + kk]);
            As[kk+0][r] = v.x; As[kk+1][r] = v.y; As[kk+2][r] = v.z; As[kk+3][r] = v.w;
        }
        #pragma unroll 2
        for (int i = tid; i < BN*4; i += NT) {
            int kk = i / (BN/4), c4 = (i % (BN/4)) * 4;
            *reinterpret_cast<float4*>(&Bs[kk][c4]) =
                *reinterpret_cast<const float4*>(&B[(size_t)(k0 + kk)*N + colBase + c4]);
        }
        __syncthreads();
        #pragma unroll
        for (int kk = 0; kk < 16; kk++) {
            unsigned long long ap[TM];
            #pragma unroll
            for (int i = 0; i < TM; i += 4) {
                float4 v = *reinterpret_cast<const float4*>(&As[kk][ty*TM + i]);
                ap[i+0] = pack2(v.x); ap[i+1] = pack2(v.y);
                ap[i+2] = pack2(v.z); ap[i+3] = pack2(v.w);
            }
            unsigned long long bp[TNH];
            #pragma unroll
            for (int j = 0; j < TNH; j += 2) {
                float4 v = *reinterpret_cast<const float4*>(&Bs[kk][tx*TN + j*2]);
                unsigned long long lo, hi;
                asm("mov.b64 %0, {%1, %2};" : "=l"(lo)
                    : "r"(__float_as_uint(v.x)), "r"(__float_as_uint(v.y)));
                asm("mov.b64 %0, {%1, %2};" : "=l"(hi)
                    : "r"(__float_as_uint(v.z)), "r"(__float_as_uint(v.w)));
                bp[j] = lo; bp[j+1] = hi;
            }
            #pragma unroll
            for (int i = 0; i < TM; i++)
                #pragma unroll
                for (int j = 0; j < TNH; j++)
                    acc[i][j] = ffma2(ap[i], bp[j], acc[i][j]);
        }
        __syncthreads();
    }
    #pragma unroll
    for (int i = 0; i < TM; i++) {
        float* cp = &C[(size_t)(rowBase + ty*TM + i)*N + colBase + tx*TN];
        #pragma unroll
        for (int j = 0; j < TNH; j += 2) {
            float4 o;
            unsigned int lx, ly, hx, hy;
            asm("mov.b64 {%0, %1}, %2;" : "=r"(lx), "=r"(ly) : "l"(acc[i][j]));
            asm("mov.b64 {%0, %1}, %2;" : "=r"(hx), "=r"(hy) : "l"(acc[i][j+1]));
            o.x = __uint_as_float(lx); o.y = __uint_as_float(ly);
            o.z = __uint_as_float(hx); o.w = __uint_as_float(hy);
            *reinterpret_cast<float4*>(cp + j*2) = o;
        }
    }
}

// ---------------- soft-edge aggregation (block per point, blockDim.x == C) -------
template<int C, int CA>
__global__ void softedge_kernel(const float* __restrict__ buf, const int* __restrict__ nbr,
                                const float* __restrict__ scale, const float* __restrict__ shift,
                                const float* __restrict__ ab,
                                const float* __restrict__ Wb, const float* __restrict__ bb,
                                float* __restrict__ fout)
{
    constexpr int STRIDE = 2*C + 2*CA;
    constexpr int AOFF = 2*C;
    const int n = blockIdx.x;
    const int t = threadIdx.x;

    __shared__ int   js[KK];
    __shared__ float wps[KK][C/32];
    __shared__ float alpha[KK];

    if (t < KK) js[t] = nbr[n*11 + 1 + t];
    __syncthreads();

    float base_a = 0.f;
    if (t < CA) {
        float usn = buf[(size_t)n*STRIDE + AOFF + t];
        base_a = buf[(size_t)n*STRIDE + AOFF + CA + t] - usn + ab[t];
    }
    #pragma unroll
    for (int k = 0; k < KK; k++) {
        float v = 0.f;
        if (t < CA) {
            float h = buf[(size_t)js[k]*STRIDE + AOFF + t] + base_a;
            h = fmaxf(h, 0.f);
            v = h * Wb[t];
        }
        #pragma unroll
        for (int off = 16; off; off >>= 1) v += __shfl_down_sync(FULLMASK, v, off);
        if ((t & 31) == 0) wps[k][t >> 5] = v;
    }
    __syncthreads();
    if (t < KK) {
        float s = 0.f;
        #pragma unroll
        for (int w = 0; w < C/32; w++) s += wps[t][w];
        alpha[t] = (s + bb[0]) / TAU;
    }
    __syncthreads();
    if (t == 0) {
        float mx = -3.4e38f;
        #pragma unroll
        for (int k = 0; k < KK; k++) mx = fmaxf(mx, alpha[k]);
        float s = 0.f;
        #pragma unroll
        for (int k = 0; k < KK; k++) { float e = expf(alpha[k] - mx); alpha[k] = e; s += e; }
        float inv = 1.f / s;
        #pragma unroll
        for (int k = 0; k < KK; k++) alpha[k] *= inv;
    }
    __syncthreads();

    float un = buf[(size_t)n*STRIDE + t];
    float w  = buf[(size_t)n*STRIDE + C + t] - un;
    float sc = scale[t], sh = shift[t];
    float acc = 0.f;
    #pragma unroll
    for (int k = 0; k < KK; k++) {
        float z = buf[(size_t)js[k]*STRIDE + t] + w;
        acc += alpha[k] * fmaxf(sc*z + sh, 0.f);
    }
    fout[(size_t)n*C + t] = acc;
}

// ---------------- final attention pooling ----------------
__global__ void wlog_kernel(const float* __restrict__ hall, const float* __restrict__ ba1,
                            const float* __restrict__ Wa2, const float* __restrict__ ba2,
                            float* __restrict__ wlog)
{
    int gw = (blockIdx.x*blockDim.x + threadIdx.x) >> 5;
    int lane = threadIdx.x & 31;
    if (gw >= BNPTS) return;
    float acc = 0.f;
    #pragma unroll
    for (int h = 0; h < 2; h++) {
        int c = lane + 32*h;
        float v = fmaxf(hall[(size_t)gw*64 + c] + ba1[c], 0.f);
        acc += v * Wa2[c];
    }
    #pragma unroll
    for (int off = 16; off; off >>= 1) acc += __shfl_down_sync(FULLMASK, acc, off);
    if (lane == 0) wlog[gw] = acc + ba2[0];
}

__global__ void batred_kernel(const float* __restrict__ wlog, float* __restrict__ bmax,
                              float* __restrict__ bsum)
{
    int b = blockIdx.x, t = threadIdx.x;
    __shared__ float red[256];
    float mx = -3.4e38f;
    for (int n = t; n < NN; n += 256) mx = fmaxf(mx, wlog[b*NN + n]);
    red[t] = mx; __syncthreads();
    for (int s = 128; s; s >>= 1) { if (t < s) red[t] = fmaxf(red[t], red[t+s]); __syncthreads(); }
    float M = red[0]; __syncthreads();
    float s = 0.f;
    for (int n = t; n < NN; n += 256) s += expf(wlog[b*NN + n] - M);
    red[t] = s; __syncthreads();
    for (int st = 128; st; st >>= 1) { if (t < st) red[t] += red[t+st]; __syncthreads(); }
    if (t == 0) { bmax[b] = M; bsum[b] = red[0]; }
}

__global__ void pool_kernel(const float* __restrict__ f3, const float* __restrict__ wlog,
                            const float* __restrict__ bmax, const float* __restrict__ bsum,
                            float* __restrict__ pooled)
{
    int b = blockIdx.y, t = threadIdx.x;
    int n0 = blockIdx.x * 256;
    __shared__ float ew[256];
    ew[t] = expf(wlog[b*NN + n0 + t] - bmax[b]) / bsum[b];
    __syncthreads();
    float acc = 0.f;
    for (int i = 0; i < 256; i++)
        acc += ew[i] * f3[((size_t)b*NN + n0 + i)*256 + t];
    atomicAdd(&pooled[b*256 + t], acc);
}

__global__ void final_kernel(const float* __restrict__ pooled, const float* __restrict__ Wfc,
                             const float* __restrict__ bfc, float* __restrict__ out)
{
    int b = blockIdx.x, t = threadIdx.x;
    __shared__ float p[256];
    p[t] = pooled[b*256 + t];
    __syncthreads();
    float acc = bfc[t];
    for (int i = 0; i < 256; i++) acc = fmaf(p[i], Wfc[i*256 + t], acc);
    out[b*256 + t] = fmaxf(acc, 0.f);
}

// ---------------- host launcher ----------------
static void* sym_addr_helper(const void* symbol)
{
    void* p = nullptr;
    cudaGetSymbolAddress(&p, symbol);
    return p;
}

extern "C" void kernel_launch(void* const* d_in, const int* in_sizes, int n_in,
                              void* d_out, int out_size)
{
    const float* x    = (const float*)d_in[0];
    const float* W1   = (const float*)d_in[1];
    const float* g1   = (const float*)d_in[2];
    const float* b1   = (const float*)d_in[3];
    const float* W2   = (const float*)d_in[4];
    const float* g2   = (const float*)d_in[5];
    const float* b2   = (const float*)d_in[6];
    const float* Ws2a = (const float*)d_in[7];
    const float* bs2a = (const float*)d_in[8];
    const float* Ws2b = (const float*)d_in[9];
    const float* bs2b = (const float*)d_in[10];
    const float* W3   = (const float*)d_in[11];
    const float* g3   = (const float*)d_in[12];
    const float* b3   = (const float*)d_in[13];
    const float* Ws3a = (const float*)d_in[14];
    const float* bs3a = (const float*)d_in[15];
    const float* Ws3b = (const float*)d_in[16];
    const float* bs3b = (const float*)d_in[17];
    const float* Wa1  = (const float*)d_in[18];
    const float* ba1  = (const float*)d_in[19];
    const float* Wa2  = (const float*)d_in[20];
    const float* ba2  = (const float*)d_in[21];
    const float* Wfc  = (const float*)d_in[22];
    const float* bfc  = (const float*)d_in[23];
    float* out = (float*)d_out;
    (void)in_sizes; (void)n_in; (void)out_size;

    int*   nbr    = (int*)  sym_addr_helper(d_nbr);
    float* buf1   = (float*)sym_addr_helper(d_buf1);
    float* m1     = (float*)sym_addr_helper(d_m1);
    float* f1     = (float*)sym_addr_helper(d_f1);
    float* buf2   = (float*)sym_addr_helper(d_buf2);
    float* f2     = (float*)sym_addr_helper(d_f2);
    float* buf3   = (float*)sym_addr_helper(d_buf3);
    float* f3     = (float*)sym_addr_helper(d_f3);
    float* hall   = (float*)sym_addr_helper(d_hall);
    float* Wc2    = (float*)sym_addr_helper(d_Wcat2);
    float* Wc3    = (float*)sym_addr_helper(d_Wcat3);
    float* stats  = (float*)sym_addr_helper(d_stats);
    float* scale  = (float*)sym_addr_helper(d_scale);
    float* shift  = (float*)sym_addr_helper(d_shift);
    float* wlog   = (float*)sym_addr_helper(d_wlog);
    float* bmax   = (float*)sym_addr_helper(d_bmax);
    float* bsum   = (float*)sym_addr_helper(d_bsum);
    float* pooled = (float*)sym_addr_helper(d_pooled);

    cudaFuncSetAttribute(knn_kernel, cudaFuncAttributeMaxDynamicSharedMemorySize, KNN_SMEM);

    // order chosen so knn is our 4th launch (ncu -s 5 -c 1 + ~2 harness
    // pre-launches should capture it next round)
    zero_all_kernel<<<14, 256>>>(stats, pooled);
    prep_kernel<<<(64*384 + 128*768 + 255)/256, 256>>>(W2, Ws2a, W3, Ws3a, Wc2, Wc3);
    uv1_kernel<<<BNPTS*64/256, 256>>>(x, W1, buf1);
    knn_kernel<<<dim3(256, BB), 128, KNN_SMEM>>>(x, nbr);

    // stage 1
    stats_kernel<<<BNPTS/16, 64>>>(buf1, 128, 0, 64, nbr, 0, 16, stats, m1);
    finalize_kernel<<<1, 64>>>(stats, g1, b1, 64, EDGE_COUNT, scale, shift);
    f1_kernel<<<BNPTS*64/256, 256>>>(m1, scale, shift, f1);

    // stage 2
    gemm_kernel<128,128,8,8,256><<<dim3(BNPTS/128, 3), 256>>>(f1, Wc2, buf2, BNPTS, 384, 64);
    stats_kernel<<<BNPTS/16, 128>>>(buf2, 384, 0, 128, nbr, 1, 16, stats + 512, nullptr);
    finalize_kernel<<<1, 128>>>(stats + 512, g2, b2, 128, EDGE_COUNT, scale + 256, shift + 256);
    softedge_kernel<128,64><<<BNPTS, 128>>>(buf2, nbr, scale + 256, shift + 256, bs2a, Ws2b, bs2b, f2);

    // stage 3
    gemm_kernel<128,128,8,8,256><<<dim3(BNPTS/128, 6), 256>>>(f2, Wc3, buf3, BNPTS, 768, 128);
    stats_kernel<<<BNPTS/8, 256>>>(buf3, 768, 0, 256, nbr, 1, 8, stats + 1024, nullptr);
    finalize_kernel<<<1, 256>>>(stats + 1024, g3, b3, 256, EDGE_COUNT, scale + 512, shift + 512);
    softedge_kernel<256,128><<<BNPTS, 256>>>(buf3, nbr, scale + 512, shift + 512, bs3a, Ws3b, bs3b, f3);

    // attention pooling + head
    gemm_kernel<128,64,8,4,256><<<dim3(BNPTS/128, 1), 256>>>(f3, Wa1, hall, BNPTS, 64, 256);
    wlog_kernel<<<BNPTS/8, 256>>>(hall, ba1, Wa2, ba2, wlog);
    batred_kernel<<<BB, 256>>>(wlog, bmax, bsum);
    pool_kernel<<<dim3(NN/256, BB), 256>>>(f3, wlog, bmax, bsum, pooled);
    final_kernel<<<BB, 256>>>(pooled, Wfc, bfc, out);
}

// round 4
// speedup vs baseline: 1.4581x; 1.3308x over previous
#include <cuda_runtime.h>
#include <cuda_bf16.h>
#include <cstdint>

#define BB 8
#define NN 4096
#define KK 10
#define BNPTS (BB*NN)          // 32768
#define EDGE_COUNT 327680.0f   // B*N*K
#define TAU 0.2f
#define EPS 1e-5f
#define FULLMASK 0xffffffffu

// ---------------- device scratch (no allocations allowed) ----------------
__device__ int   d_nbr[BNPTS*11];
__device__ float d_buf1[BNPTS*128];     // u1(64)|v1(64)
__device__ float d_m1[BNPTS*64];        // max_k z (stage1)
__device__ float d_f1[BNPTS*64];
__device__ float d_buf2[BNPTS*384];     // u2(128)|v2(128)|us2(64)|vs2(64)
__device__ float d_f2[BNPTS*128];
__device__ float d_buf3[BNPTS*768];     // u3(256)|v3(256)|us3(128)|vs3(128)
__device__ float d_f3[BNPTS*256];
__device__ float d_hall[BNPTS*64];
__device__ float d_Wcat2[64*384];
__device__ float d_Wcat3[128*768];
__device__ float d_stats[3*512];
__device__ float d_scale[3*256];
__device__ float d_shift[3*256];
__device__ float d_wlog[BNPTS];
__device__ float d_bmax[BB];
__device__ float d_bsum[BB];
__device__ float d_pooled[BB*256];

// ---------------- packed f32x2 fma ----------------
__device__ __forceinline__ unsigned long long ffma2(unsigned long long a,
                                                    unsigned long long b,
                                                    unsigned long long c)
{
    unsigned long long d;
    asm("fma.rn.f32x2 %0, %1, %2, %3;" : "=l"(d) : "l"(a), "l"(b), "l"(c));
    return d;
}
__device__ __forceinline__ unsigned long long pack2(float x)
{
    unsigned long long d;
    asm("mov.b64 %0, {%1, %1};" : "=l"(d) : "r"(__float_as_uint(x)));
    return d;
}

// ---------------- zero all accumulators ----------------
__global__ void zero_all_kernel(float* __restrict__ stats, float* __restrict__ pooled)
{
    int i = blockIdx.x*blockDim.x + threadIdx.x;
    if (i < 3*512) stats[i] = 0.f;
    if (i < BB*256) pooled[i] = 0.f;
}

// ---------------- KNN: threshold-filter top-11 ----------------
#define KNN_WARPS 8
#define KNN_QPW 8
#define KNN_BUF 128
#define KNN_SMEM (4096*16 + KNN_WARPS*KNN_BUF*8 + KNN_WARPS*4)

__device__ __forceinline__ unsigned orderable_f32(float f)
{
    unsigned u = __float_as_uint(f);
    return (u & 0x80000000u) ? ~u : (u | 0x80000000u);
}

__global__ __launch_bounds__(KNN_WARPS*32) void knn_kernel(
    const float* __restrict__ x, int* __restrict__ nbr)
{
    extern __shared__ unsigned char smem_raw[];
    float4* cand = (float4*)smem_raw;
    unsigned long long* wbuf = (unsigned long long*)(cand + 4096);
    int* wcnt = (int*)(wbuf + KNN_WARPS*KNN_BUF);

    const int b    = blockIdx.y;
    const int tid  = threadIdx.x;
    const int warp = tid >> 5;
    const int lane = tid & 31;

    for (int i = tid; i < 4096; i += blockDim.x) {
        const float* xp = x + ((size_t)b*4096 + i)*5;
        float cx = xp[0], cy = xp[1], cz = xp[2];
        cand[i] = make_float4(cx, cy, cz, cx*cx + cy*cy + cz*cz);
    }
    __syncthreads();

    unsigned long long* buf = wbuf + warp*KNN_BUF;

    for (int qi = 0; qi < KNN_QPW; qi++) {
        const int q = blockIdx.x*(KNN_WARPS*KNN_QPW) + warp*KNN_QPW + qi;
        const float4 Q = cand[q];
        const float m2x = -2.f*Q.x, m2y = -2.f*Q.y, m2z = -2.f*Q.z;

        // ---- phase 1: per-lane minimum (branchless) ----
        float lmin = 3.4e38f;
        #pragma unroll 4
        for (int m = lane; m < 4096; m += 32) {
            float4 c = cand[m];
            float key = fmaf(c.x, m2x, fmaf(c.y, m2y, fmaf(c.z, m2z, c.w)));
            lmin = fminf(lmin, key);
        }

        // ---- threshold tau = 11th smallest of the 32 lane minima ----
        float val = lmin, tau = 0.f;
        #pragma unroll
        for (int r = 0; r < 11; r++) {
            float mn = val;
            #pragma unroll
            for (int off = 16; off; off >>= 1)
                mn = fminf(mn, __shfl_xor_sync(FULLMASK, mn, off));
            tau = mn;
            unsigned bal = __ballot_sync(FULLMASK, val == mn);
            if (lane == __ffs(bal) - 1) val = 3.4e38f;
        }

        // ---- phase 2: collect candidates with key <= tau ----
        if (lane == 0) wcnt[warp] = 0;
        __syncwarp();
        #pragma unroll 2
        for (int m = lane; m < 4096; m += 32) {
            float4 c = cand[m];
            float key = fmaf(c.x, m2x, fmaf(c.y, m2y, fmaf(c.z, m2z, c.w)));
            bool p = (key <= tau);
            unsigned mask = __ballot_sync(FULLMASK, p);
            if (mask) {
                int base = 0;
                if (lane == 0) { base = wcnt[warp]; wcnt[warp] = base + __popc(mask); }
                base = __shfl_sync(FULLMASK, base, 0);
                if (p) {
                    int pos = base + __popc(mask & ((1u << lane) - 1));
                    if (pos < KNN_BUF)
                        buf[pos] = ((unsigned long long)orderable_f32(key) << 32)
                                 | (unsigned)m;
                }
            }
        }
        __syncwarp();
        const int cnt = wcnt[warp];

        if (cnt <= KNN_BUF) {
            // ---- phase 3: 11 exact min-extractions from the small buffer ----
            unsigned long long v[KNN_BUF/32];
            #pragma unroll
            for (int j = 0; j < KNN_BUF/32; j++) {
                int idx = lane + 32*j;
                v[j] = (idx < cnt) ? buf[idx] : 0xffffffffffffffffull;
            }
            #pragma unroll
            for (int r = 0; r < 11; r++) {
                unsigned long long mn = v[0];
                #pragma unroll
                for (int j = 1; j < KNN_BUF/32; j++) mn = min(mn, v[j]);
                #pragma unroll
                for (int off = 16; off; off >>= 1) {
                    unsigned long long o = __shfl_xor_sync(FULLMASK, mn, off);
                    if (o < mn) mn = o;
                }
                #pragma unroll
                for (int j = 0; j < KNN_BUF/32; j++)
                    if (v[j] == mn) v[j] = 0xffffffffffffffffull;
                if (lane == 0)
                    nbr[((size_t)b*4096 + q)*11 + r] = b*4096 + (int)(mn & 0xffffffffu);
            }
        } else {
            // ---- overflow fallback: exact 11 rounds of min-with-exclusion ----
            unsigned long long last = 0ull;
            for (int r = 0; r < 11; r++) {
                unsigned long long lm = 0xffffffffffffffffull;
                for (int m = lane; m < 4096; m += 32) {
                    float4 c = cand[m];
                    float key = fmaf(c.x, m2x, fmaf(c.y, m2y, fmaf(c.z, m2z, c.w)));
                    unsigned long long pk =
                        ((unsigned long long)orderable_f32(key) << 32) | (unsigned)m;
                    if (pk > last && pk < lm) lm = pk;
                }
                unsigned long long mn = lm;
                #pragma unroll
                for (int off = 16; off; off >>= 1) {
                    unsigned long long o = __shfl_xor_sync(FULLMASK, mn, off);
                    if (o < mn) mn = o;
                }
                last = mn;
                if (lane == 0)
                    nbr[((size_t)b*4096 + q)*11 + r] = b*4096 + (int)(mn & 0xffffffffu);
            }
        }
    }
}

// ---------------- weight prep: concat split matrices ----------------
__global__ void prep_kernel(const float* __restrict__ W2, const float* __restrict__ Ws2a,
                            const float* __restrict__ W3, const float* __restrict__ Ws3a,
                            float* __restrict__ Wc2, float* __restrict__ Wc3)
{
    int i = blockIdx.x*blockDim.x + threadIdx.x;
    if (i < 64*384) {
        int r = i/384, c = i%384;
        float v;
        if      (c < 128) v = W2[r*128 + c];
        else if (c < 256) v = W2[(64+r)*128 + (c-128)];
        else if (c < 320) v = Ws2a[r*64 + (c-256)];
        else              v = Ws2a[(64+r)*64 + (c-320)];
        Wc2[i] = v;
    } else {
        int j = i - 64*384;
        if (j < 128*768) {
            int r = j/768, c = j%768;
            float v;
            if      (c < 256) v = W3[r*256 + c];
            else if (c < 512) v = W3[(128+r)*256 + (c-256)];
            else if (c < 640) v = Ws3a[r*128 + (c-512)];
            else              v = Ws3a[(128+r)*128 + (c-640)];
            Wc3[j] = v;
        }
    }
}

// ---------------- stage-1 u/v ----------------
__global__ void uv1_kernel(const float* __restrict__ x, const float* __restrict__ W1,
                           float* __restrict__ buf1)
{
    int idx = blockIdx.x*blockDim.x + threadIdx.x;
    if (idx >= BNPTS*64) return;
    int n = idx >> 6, c = idx & 63;
    const float* xp = x + (size_t)n*5;
    float x0 = xp[0], x1 = xp[1], x2 = xp[2], x3 = xp[3], x4 = xp[4];
    float u = x0*W1[0*64+c] + x1*W1[1*64+c] + x2*W1[2*64+c] + x3*W1[6*64+c] + x4*W1[7*64+c];
    float v = x0*W1[3*64+c] + x1*W1[4*64+c] + x2*W1[5*64+c] + x3*W1[8*64+c] + x4*W1[9*64+c];
    buf1[n*128 + c]      = u;
    buf1[n*128 + 64 + c] = v;
}

// ---------------- BN statistics over edges ----------------
__global__ void stats_kernel(const float* __restrict__ buf, int stride, int uoff, int voff,
                             const int* __restrict__ nbr, int koff, int ppb,
                             float* __restrict__ stats, float* __restrict__ maxOut)
{
    const int c = threadIdx.x;
    const int C = blockDim.x;
    const int p0 = blockIdx.x * ppb;
    float sum = 0.f, ss = 0.f;
    for (int p = 0; p < ppb; p++) {
        int n = p0 + p;
        float un = buf[(size_t)n*stride + uoff + c];
        float vn = buf[(size_t)n*stride + voff + c];
        float w = vn - un;
        float mx = -3.4e38f;
        #pragma unroll
        for (int k = 0; k < KK; k++) {
            int j = nbr[n*11 + koff + k];
            float z = buf[(size_t)j*stride + uoff + c] + w;
            sum += z; ss += z*z;
            mx = fmaxf(mx, z);
        }
        if (maxOut) maxOut[(size_t)n*C + c] = mx;
    }
    atomicAdd(&stats[c], sum);
    atomicAdd(&stats[256 + c], ss);
}

__global__ void finalize_kernel(const float* __restrict__ stats,
                                const float* __restrict__ g, const float* __restrict__ bb,
                                int C, float cnt,
                                float* __restrict__ scale, float* __restrict__ shift)
{
    int c = blockIdx.x*blockDim.x + threadIdx.x;
    if (c >= C) return;
    float mean = stats[c] / cnt;
    float var  = stats[256 + c] / cnt - mean*mean;
    float rs = rsqrtf(var + EPS);
    float sc = g[c]*rs;
    scale[c] = sc;
    shift[c] = bb[c] - mean*sc;
}

// ---------------- f1 = relu(scale*max + shift) ----------------
__global__ void f1_kernel(const float* __restrict__ m1, const float* __restrict__ scale,
                          const float* __restrict__ shift, float* __restrict__ f1)
{
    int idx = blockIdx.x*blockDim.x + threadIdx.x;
    if (idx >= BNPTS*64) return;
    int c = idx & 63;
    f1[idx] = fmaxf(scale[c]*m1[idx] + shift[c], 0.f);
}

// ---------------- fp32 tiled GEMM with packed f32x2 accumulate ----------------
template<int BM, int BN, int TM, int TN, int NT>
__global__ __launch_bounds__(NT) void gemm_kernel(
    const float* __restrict__ A, const float* __restrict__ B, float* __restrict__ C,
    int M, int N, int Kd)
{
    __shared__ __align__(16) float As[16][BM + 4];
    __shared__ __align__(16) float Bs[16][BN];
    const int tid = threadIdx.x;
    constexpr int TX = BN / TN;
    constexpr int TNH = TN / 2;
    const int tx = tid % TX;
    const int ty = tid / TX;
    const int rowBase = blockIdx.x * BM;
    const int colBase = blockIdx.y * BN;

    unsigned long long acc[TM][TNH];
    #pragma unroll
    for (int i = 0; i < TM; i++)
        #pragma unroll
        for (int j = 0; j < TNH; j++) acc[i][j] = 0ull;

    for (int k0 = 0; k0 < Kd; k0 += 16) {
        #pragma unroll 2
        for (int i = tid; i < BM*4; i += NT) {
            int r = i >> 2, kk = (i & 3) * 4;
            const float4 v = *reinterpret_cast<const float4*>(
                &A[(size_t)(rowBase + r)*Kd + k0 + kk]);
            As[kk+0][r] = v.x; As[kk+1][r] = v.y; As[kk+2][r] = v.z; As[kk+3][r] = v.w;
        }
        #pragma unroll 2
        for (int i = tid; i < BN*4; i += NT) {
            int kk = i / (BN/4), c4 = (i % (BN/4)) * 4;
            *reinterpret_cast<float4*>(&Bs[kk][c4]) =
                *reinterpret_cast<const float4*>(&B[(size_t)(k0 + kk)*N + colBase + c4]);
        }
        __syncthreads();
        #pragma unroll
        for (int kk = 0; kk < 16; kk++) {
            unsigned long long ap[TM];
            #pragma unroll
            for (int i = 0; i < TM; i += 4) {
                float4 v = *reinterpret_cast<const float4*>(&As[kk][ty*TM + i]);
                ap[i+0] = pack2(v.x); ap[i+1] = pack2(v.y);
                ap[i+2] = pack2(v.z); ap[i+3] = pack2(v.w);
            }
            unsigned long long bp[TNH];
            #pragma unroll
            for (int j = 0; j < TNH; j += 2) {
                float4 v = *reinterpret_cast<const float4*>(&Bs[kk][tx*TN + j*2]);
                unsigned long long lo, hi;
                asm("mov.b64 %0, {%1, %2};" : "=l"(lo)
                    : "r"(__float_as_uint(v.x)), "r"(__float_as_uint(v.y)));
                asm("mov.b64 %0, {%1, %2};" : "=l"(hi)
                    : "r"(__float_as_uint(v.z)), "r"(__float_as_uint(v.w)));
                bp[j] = lo; bp[j+1] = hi;
            }
            #pragma unroll
            for (int i = 0; i < TM; i++)
                #pragma unroll
                for (int j = 0; j < TNH; j++)
                    acc[i][j] = ffma2(ap[i], bp[j], acc[i][j]);
        }
        __syncthreads();
    }
    #pragma unroll
    for (int i = 0; i < TM; i++) {
        float* cp = &C[(size_t)(rowBase + ty*TM + i)*N + colBase + tx*TN];
        #pragma unroll
        for (int j = 0; j < TNH; j += 2) {
            float4 o;
            unsigned int lx, ly, hx, hy;
            asm("mov.b64 {%0, %1}, %2;" : "=r"(lx), "=r"(ly) : "l"(acc[i][j]));
            asm("mov.b64 {%0, %1}, %2;" : "=r"(hx), "=r"(hy) : "l"(acc[i][j+1]));
            o.x = __uint_as_float(lx); o.y = __uint_as_float(ly);
            o.z = __uint_as_float(hx); o.w = __uint_as_float(hy);
            *reinterpret_cast<float4*>(cp + j*2) = o;
        }
    }
}

// ---------------- soft-edge aggregation ----------------
template<int C, int CA>
__global__ void softedge_kernel(const float* __restrict__ buf, const int* __restrict__ nbr,
                                const float* __restrict__ scale, const float* __restrict__ shift,
                                const float* __restrict__ ab,
                                const float* __restrict__ Wb, const float* __restrict__ bb,
                                float* __restrict__ fout)
{
    constexpr int STRIDE = 2*C + 2*CA;
    constexpr int AOFF = 2*C;
    const int n = blockIdx.x;
    const int t = threadIdx.x;

    __shared__ int   js[KK];
    __shared__ float wps[KK][C/32];
    __shared__ float alpha[KK];

    if (t < KK) js[t] = nbr[n*11 + 1 + t];
    __syncthreads();

    float base_a = 0.f;
    if (t < CA) {
        float usn = buf[(size_t)n*STRIDE + AOFF + t];
        base_a = buf[(size_t)n*STRIDE + AOFF + CA + t] - usn + ab[t];
    }
    #pragma unroll
    for (int k = 0; k < KK; k++) {
        float v = 0.f;
        if (t < CA) {
            float h = buf[(size_t)js[k]*STRIDE + AOFF + t] + base_a;
            h = fmaxf(h, 0.f);
            v = h * Wb[t];
        }
        #pragma unroll
        for (int off = 16; off; off >>= 1) v += __shfl_down_sync(FULLMASK, v, off);
        if ((t & 31) == 0) wps[k][t >> 5] = v;
    }
    __syncthreads();
    if (t < KK) {
        float s = 0.f;
        #pragma unroll
        for (int w = 0; w < C/32; w++) s += wps[t][w];
        alpha[t] = (s + bb[0]) / TAU;
    }
    __syncthreads();
    if (t == 0) {
        float mx = -3.4e38f;
        #pragma unroll
        for (int k = 0; k < KK; k++) mx = fmaxf(mx, alpha[k]);
        float s = 0.f;
        #pragma unroll
        for (int k = 0; k < KK; k++) { float e = expf(alpha[k] - mx); alpha[k] = e; s += e; }
        float inv = 1.f / s;
        #pragma unroll
        for (int k = 0; k < KK; k++) alpha[k] *= inv;
    }
    __syncthreads();

    float un = buf[(size_t)n*STRIDE + t];
    float w  = buf[(size_t)n*STRIDE + C + t] - un;
    float sc = scale[t], sh = shift[t];
    float acc = 0.f;
    #pragma unroll
    for (int k = 0; k < KK; k++) {
        float z = buf[(size_t)js[k]*STRIDE + t] + w;
        acc += alpha[k] * fmaxf(sc*z + sh, 0.f);
    }
    fout[(size_t)n*C + t] = acc;
}

// ---------------- final attention pooling ----------------
__global__ void wlog_kernel(const float* __restrict__ hall, const float* __restrict__ ba1,
                            const float* __restrict__ Wa2, const float* __restrict__ ba2,
                            float* __restrict__ wlog)
{
    int gw = (blockIdx.x*blockDim.x + threadIdx.x) >> 5;
    int lane = threadIdx.x & 31;
    if (gw >= BNPTS) return;
    float acc = 0.f;
    #pragma unroll
    for (int h = 0; h < 2; h++) {
        int c = lane + 32*h;
        float v = fmaxf(hall[(size_t)gw*64 + c] + ba1[c], 0.f);
        acc += v * Wa2[c];
    }
    #pragma unroll
    for (int off = 16; off; off >>= 1) acc += __shfl_down_sync(FULLMASK, acc, off);
    if (lane == 0) wlog[gw] = acc + ba2[0];
}

__global__ void batred_kernel(const float* __restrict__ wlog, float* __restrict__ bmax,
                              float* __restrict__ bsum)
{
    int b = blockIdx.x, t = threadIdx.x;
    __shared__ float red[256];
    float mx = -3.4e38f;
    for (int n = t; n < NN; n += 256) mx = fmaxf(mx, wlog[b*NN + n]);
    red[t] = mx; __syncthreads();
    for (int s = 128; s; s >>= 1) { if (t < s) red[t] = fmaxf(red[t], red[t+s]); __syncthreads(); }
    float M = red[0]; __syncthreads();
    float s = 0.f;
    for (int n = t; n < NN; n += 256) s += expf(wlog[b*NN + n] - M);
    red[t] = s; __syncthreads();
    for (int st = 128; st; st >>= 1) { if (t < st) red[t] += red[t+st]; __syncthreads(); }
    if (t == 0) { bmax[b] = M; bsum[b] = red[0]; }
}

__global__ void pool_kernel(const float* __restrict__ f3, const float* __restrict__ wlog,
                            const float* __restrict__ bmax, const float* __restrict__ bsum,
                            float* __restrict__ pooled)
{
    int b = blockIdx.y, t = threadIdx.x;
    int n0 = blockIdx.x * 256;
    __shared__ float ew[256];
    ew[t] = expf(wlog[b*NN + n0 + t] - bmax[b]) / bsum[b];
    __syncthreads();
    float acc = 0.f;
    for (int i = 0; i < 256; i++)
        acc += ew[i] * f3[((size_t)b*NN + n0 + i)*256 + t];
    atomicAdd(&pooled[b*256 + t], acc);
}

__global__ void final_kernel(const float* __restrict__ pooled, const float* __restrict__ Wfc,
                             const float* __restrict__ bfc, float* __restrict__ out)
{
    int b = blockIdx.x, t = threadIdx.x;
    __shared__ float p[256];
    p[t] = pooled[b*256 + t];
    __syncthreads();
    float acc = bfc[t];
    for (int i = 0; i < 256; i++) acc = fmaf(p[i], Wfc[i*256 + t], acc);
    out[b*256 + t] = fmaxf(acc, 0.f);
}

// ---------------- host launcher ----------------
static void* sym_addr_helper(const void* symbol)
{
    void* p = nullptr;
    cudaGetSymbolAddress(&p, symbol);
    return p;
}

extern "C" void kernel_launch(void* const* d_in, const int* in_sizes, int n_in,
                              void* d_out, int out_size)
{
    const float* x    = (const float*)d_in[0];
    const float* W1   = (const float*)d_in[1];
    const float* g1   = (const float*)d_in[2];
    const float* b1   = (const float*)d_in[3];
    const float* W2   = (const float*)d_in[4];
    const float* g2   = (const float*)d_in[5];
    const float* b2   = (const float*)d_in[6];
    const float* Ws2a = (const float*)d_in[7];
    const float* bs2a = (const float*)d_in[8];
    const float* Ws2b = (const float*)d_in[9];
    const float* bs2b = (const float*)d_in[10];
    const float* W3   = (const float*)d_in[11];
    const float* g3   = (const float*)d_in[12];
    const float* b3   = (const float*)d_in[13];
    const float* Ws3a = (const float*)d_in[14];
    const float* bs3a = (const float*)d_in[15];
    const float* Ws3b = (const float*)d_in[16];
    const float* bs3b = (const float*)d_in[17];
    const float* Wa1  = (const float*)d_in[18];
    const float* ba1  = (const float*)d_in[19];
    const float* Wa2  = (const float*)d_in[20];
    const float* ba2  = (const float*)d_in[21];
    const float* Wfc  = (const float*)d_in[22];
    const float* bfc  = (const float*)d_in[23];
    float* out = (float*)d_out;
    (void)in_sizes; (void)n_in; (void)out_size;

    int*   nbr    = (int*)  sym_addr_helper(d_nbr);
    float* buf1   = (float*)sym_addr_helper(d_buf1);
    float* m1     = (float*)sym_addr_helper(d_m1);
    float* f1     = (float*)sym_addr_helper(d_f1);
    float* buf2   = (float*)sym_addr_helper(d_buf2);
    float* f2     = (float*)sym_addr_helper(d_f2);
    float* buf3   = (float*)sym_addr_helper(d_buf3);
    float* f3     = (float*)sym_addr_helper(d_f3);
    float* hall   = (float*)sym_addr_helper(d_hall);
    float* Wc2    = (float*)sym_addr_helper(d_Wcat2);
    float* Wc3    = (float*)sym_addr_helper(d_Wcat3);
    float* stats  = (float*)sym_addr_helper(d_stats);
    float* scale  = (float*)sym_addr_helper(d_scale);
    float* shift  = (float*)sym_addr_helper(d_shift);
    float* wlog   = (float*)sym_addr_helper(d_wlog);
    float* bmax   = (float*)sym_addr_helper(d_bmax);
    float* bsum   = (float*)sym_addr_helper(d_bsum);
    float* pooled = (float*)sym_addr_helper(d_pooled);

    cudaFuncSetAttribute(knn_kernel, cudaFuncAttributeMaxDynamicSharedMemorySize, KNN_SMEM);

    // keep knn as our 4th launch so ncu recaptures it (verify the win)
    zero_all_kernel<<<14, 256>>>(stats, pooled);
    prep_kernel<<<(64*384 + 128*768 + 255)/256, 256>>>(W2, Ws2a, W3, Ws3a, Wc2, Wc3);
    uv1_kernel<<<BNPTS*64/256, 256>>>(x, W1, buf1);
    knn_kernel<<<dim3(4096/(KNN_WARPS*KNN_QPW), BB), KNN_WARPS*32, KNN_SMEM>>>(x, nbr);

    // stage 1
    stats_kernel<<<BNPTS/16, 64>>>(buf1, 128, 0, 64, nbr, 0, 16, stats, m1);
    finalize_kernel<<<1, 64>>>(stats, g1, b1, 64, EDGE_COUNT, scale, shift);
    f1_kernel<<<BNPTS*64/256, 256>>>(m1, scale, shift, f1);

    // stage 2
    gemm_kernel<128,128,8,8,256><<<dim3(BNPTS/128, 3), 256>>>(f1, Wc2, buf2, BNPTS, 384, 64);
    stats_kernel<<<BNPTS/16, 128>>>(buf2, 384, 0, 128, nbr, 1, 16, stats + 512, nullptr);
    finalize_kernel<<<1, 128>>>(stats + 512, g2, b2, 128, EDGE_COUNT, scale + 256, shift + 256);
    softedge_kernel<128,64><<<BNPTS, 128>>>(buf2, nbr, scale + 256, shift + 256, bs2a, Ws2b, bs2b, f2);

    // stage 3
    gemm_kernel<128,128,8,8,256><<<dim3(BNPTS/128, 6), 256>>>(f2, Wc3, buf3, BNPTS, 768, 128);
    stats_kernel<<<BNPTS/8, 256>>>(buf3, 768, 0, 256, nbr, 1, 8, stats + 1024, nullptr);
    finalize_kernel<<<1, 256>>>(stats + 1024, g3, b3, 256, EDGE_COUNT, scale + 512, shift + 512);
    softedge_kernel<256,128><<<BNPTS, 256>>>(buf3, nbr, scale + 512, shift + 512, bs3a, Ws3b, bs3b, f3);

    // attention pooling + head
    gemm_kernel<128,64,8,4,256><<<dim3(BNPTS/128, 1), 256>>>(f3, Wa1, hall, BNPTS, 64, 256);
    wlog_kernel<<<BNPTS/8, 256>>>(hall, ba1, Wa2, ba2, wlog);
    batred_kernel<<<BB, 256>>>(wlog, bmax, bsum);
    pool_kernel<<<dim3(NN/256, BB), 256>>>(f3, wlog, bmax, bsum, pooled);
    final_kernel<<<BB, 256>>>(pooled, Wfc, bfc, out);
}

// round 5
// speedup vs baseline: 1.5969x; 1.0952x over previous
#include <cuda_runtime.h>
#include <cuda_bf16.h>
#include <cstdint>

#define BB 8
#define NN 4096
#define KK 10
#define BNPTS (BB*NN)          // 32768
#define EDGE_COUNT 327680.0f   // B*N*K
#define TAU 0.2f
#define EPS 1e-5f
#define FULLMASK 0xffffffffu

// ---------------- device scratch (no allocations allowed) ----------------
__device__ int   d_nbr[BNPTS*11];
__device__ float d_buf1[BNPTS*128];     // u1(64)|v1(64)
__device__ float d_m1[BNPTS*64];        // max_k z (stage1)
__device__ float d_f1[BNPTS*64];
__device__ float d_buf2[BNPTS*384];     // u2(128)|v2(128)|us2(64)|vs2(64)
__device__ float d_f2[BNPTS*128];
__device__ float d_buf3[BNPTS*768];     // u3(256)|v3(256)|us3(128)|vs3(128)
__device__ float d_f3[BNPTS*256];
__device__ float d_hall[BNPTS*64];
__device__ float d_Wcat2[64*384];
__device__ float d_Wcat3[128*768];
__device__ float d_stats[3*512];
__device__ float d_scale[3*256];
__device__ float d_shift[3*256];
__device__ float d_wlog[BNPTS];
__device__ float d_bmax[BB];
__device__ float d_bsum[BB];
__device__ float d_pooled[BB*256];

// ---------------- packed f32x2 fma ----------------
__device__ __forceinline__ unsigned long long ffma2(unsigned long long a,
                                                    unsigned long long b,
                                                    unsigned long long c)
{
    unsigned long long d;
    asm("fma.rn.f32x2 %0, %1, %2, %3;" : "=l"(d) : "l"(a), "l"(b), "l"(c));
    return d;
}
__device__ __forceinline__ unsigned long long pack2(float x)
{
    unsigned long long d;
    asm("mov.b64 %0, {%1, %1};" : "=l"(d) : "r"(__float_as_uint(x)));
    return d;
}

// ---------------- zero all accumulators ----------------
__global__ void zero_all_kernel(float* __restrict__ stats, float* __restrict__ pooled)
{
    int i = blockIdx.x*blockDim.x + threadIdx.x;
    if (i < 3*512) stats[i] = 0.f;
    if (i < BB*256) pooled[i] = 0.f;
}

// ---------------- KNN: threshold-filter top-11, 8 queries per warp pass ----------
#define KNN_WARPS 8
#define KNN_QB 8            // queries processed simultaneously per warp
#define KNN_BUF 64          // slots per query
#define KNN_SMEM (4096*16 + KNN_WARPS*KNN_QB*KNN_BUF*8)

__device__ __forceinline__ unsigned orderable_f32(float f)
{
    unsigned u = __float_as_uint(f);
    return (u & 0x80000000u) ? ~u : (u | 0x80000000u);
}

__global__ __launch_bounds__(KNN_WARPS*32) void knn_kernel(
    const float* __restrict__ x, int* __restrict__ nbr)
{
    extern __shared__ unsigned char smem_raw[];
    float4* cand = (float4*)smem_raw;
    unsigned long long* wbuf = (unsigned long long*)(cand + 4096);

    const int b    = blockIdx.y;
    const int tid  = threadIdx.x;
    const int warp = tid >> 5;
    const int lane = tid & 31;

    for (int i = tid; i < 4096; i += blockDim.x) {
        const float* xp = x + ((size_t)b*4096 + i)*5;
        float cx = xp[0], cy = xp[1], cz = xp[2];
        cand[i] = make_float4(cx, cy, cz, cx*cx + cy*cy + cz*cz);
    }
    __syncthreads();

    const int qbase = blockIdx.x*(KNN_WARPS*KNN_QB) + warp*KNN_QB;
    unsigned long long* bufw = wbuf + (size_t)warp*KNN_QB*KNN_BUF;

    // query coefficients
    float m2x[KNN_QB], m2y[KNN_QB], m2z[KNN_QB];
    #pragma unroll
    for (int j = 0; j < KNN_QB; j++) {
        float4 Q = cand[qbase + j];
        m2x[j] = -2.f*Q.x; m2y[j] = -2.f*Q.y; m2z[j] = -2.f*Q.z;
    }

    // ---- phase 1: per-lane minima for all 8 queries in one scan ----
    float lmin[KNN_QB];
    #pragma unroll
    for (int j = 0; j < KNN_QB; j++) lmin[j] = 3.4e38f;
    for (int m = lane; m < 4096; m += 32) {
        float4 c = cand[m];
        #pragma unroll
        for (int j = 0; j < KNN_QB; j++) {
            float key = fmaf(c.x, m2x[j], fmaf(c.y, m2y[j], fmaf(c.z, m2z[j], c.w)));
            lmin[j] = fminf(lmin[j], key);
        }
    }

    // ---- thresholds: tau[j] = 11th smallest of the 32 lane minima ----
    float tau[KNN_QB];
    #pragma unroll
    for (int j = 0; j < KNN_QB; j++) {
        float val = lmin[j], t = 0.f;
        #pragma unroll
        for (int r = 0; r < 11; r++) {
            float mn = val;
            #pragma unroll
            for (int off = 16; off; off >>= 1)
                mn = fminf(mn, __shfl_xor_sync(FULLMASK, mn, off));
            t = mn;
            unsigned bal = __ballot_sync(FULLMASK, val == mn);
            if (lane == __ffs(bal) - 1) val = 3.4e38f;
        }
        tau[j] = t;
    }

    // ---- phase 2: one scan, collect candidates <= tau[j] into per-query bufs ----
    int cnt[KNN_QB];
    #pragma unroll
    for (int j = 0; j < KNN_QB; j++) cnt[j] = 0;
    const unsigned lt = (1u << lane) - 1u;
    for (int m = lane; m < 4096; m += 32) {
        float4 c = cand[m];
        #pragma unroll
        for (int j = 0; j < KNN_QB; j++) {
            float key = fmaf(c.x, m2x[j], fmaf(c.y, m2y[j], fmaf(c.z, m2z[j], c.w)));
            bool p = (key <= tau[j]);
            unsigned mask = __ballot_sync(FULLMASK, p);
            if (p) {
                int pos = cnt[j] + __popc(mask & lt);
                if (pos < KNN_BUF)
                    bufw[j*KNN_BUF + pos] =
                        ((unsigned long long)orderable_f32(key) << 32) | (unsigned)m;
            }
            cnt[j] += __popc(mask);
        }
    }
    __syncwarp();

    // ---- phase 3: exact top-11 per query ----
    #pragma unroll
    for (int j = 0; j < KNN_QB; j++) {
        const int q = qbase + j;
        if (cnt[j] <= KNN_BUF) {
            unsigned long long v0, v1;
            v0 = (lane      < cnt[j]) ? bufw[j*KNN_BUF + lane]      : 0xffffffffffffffffull;
            v1 = (lane + 32 < cnt[j]) ? bufw[j*KNN_BUF + lane + 32] : 0xffffffffffffffffull;
            #pragma unroll
            for (int r = 0; r < 11; r++) {
                unsigned long long mn = min(v0, v1);
                #pragma unroll
                for (int off = 16; off; off >>= 1) {
                    unsigned long long o = __shfl_xor_sync(FULLMASK, mn, off);
                    if (o < mn) mn = o;
                }
                if (v0 == mn) v0 = 0xffffffffffffffffull;
                if (v1 == mn) v1 = 0xffffffffffffffffull;
                if (lane == 0)
                    nbr[((size_t)b*4096 + q)*11 + r] = b*4096 + (int)(mn & 0xffffffffu);
            }
        } else {
            // overflow fallback: exact 11 rounds of min-with-exclusion over all
            unsigned long long last = 0ull;
            for (int r = 0; r < 11; r++) {
                unsigned long long lm = 0xffffffffffffffffull;
                for (int m = lane; m < 4096; m += 32) {
                    float4 c = cand[m];
                    float key = fmaf(c.x, m2x[j], fmaf(c.y, m2y[j], fmaf(c.z, m2z[j], c.w)));
                    unsigned long long pk =
                        ((unsigned long long)orderable_f32(key) << 32) | (unsigned)m;
                    if (pk > last && pk < lm) lm = pk;
                }
                unsigned long long mn = lm;
                #pragma unroll
                for (int off = 16; off; off >>= 1) {
                    unsigned long long o = __shfl_xor_sync(FULLMASK, mn, off);
                    if (o < mn) mn = o;
                }
                last = mn;
                if (lane == 0)
                    nbr[((size_t)b*4096 + q)*11 + r] = b*4096 + (int)(mn & 0xffffffffu);
            }
        }
    }
}

// ---------------- weight prep: concat split matrices ----------------
__global__ void prep_kernel(const float* __restrict__ W2, const float* __restrict__ Ws2a,
                            const float* __restrict__ W3, const float* __restrict__ Ws3a,
                            float* __restrict__ Wc2, float* __restrict__ Wc3)
{
    int i = blockIdx.x*blockDim.x + threadIdx.x;
    if (i < 64*384) {
        int r = i/384, c = i%384;
        float v;
        if      (c < 128) v = W2[r*128 + c];
        else if (c < 256) v = W2[(64+r)*128 + (c-128)];
        else if (c < 320) v = Ws2a[r*64 + (c-256)];
        else              v = Ws2a[(64+r)*64 + (c-320)];
        Wc2[i] = v;
    } else {
        int j = i - 64*384;
        if (j < 128*768) {
            int r = j/768, c = j%768;
            float v;
            if      (c < 256) v = W3[r*256 + c];
            else if (c < 512) v = W3[(128+r)*256 + (c-256)];
            else if (c < 640) v = Ws3a[r*128 + (c-512)];
            else              v = Ws3a[(128+r)*128 + (c-640)];
            Wc3[j] = v;
        }
    }
}

// ---------------- stage-1 u/v ----------------
__global__ void uv1_kernel(const float* __restrict__ x, const float* __restrict__ W1,
                           float* __restrict__ buf1)
{
    int idx = blockIdx.x*blockDim.x + threadIdx.x;
    if (idx >= BNPTS*64) return;
    int n = idx >> 6, c = idx & 63;
    const float* xp = x + (size_t)n*5;
    float x0 = xp[0], x1 = xp[1], x2 = xp[2], x3 = xp[3], x4 = xp[4];
    float u = x0*W1[0*64+c] + x1*W1[1*64+c] + x2*W1[2*64+c] + x3*W1[6*64+c] + x4*W1[7*64+c];
    float v = x0*W1[3*64+c] + x1*W1[4*64+c] + x2*W1[5*64+c] + x3*W1[8*64+c] + x4*W1[9*64+c];
    buf1[n*128 + c]      = u;
    buf1[n*128 + 64 + c] = v;
}

// ---------------- BN statistics over edges ----------------
__global__ void stats_kernel(const float* __restrict__ buf, int stride, int uoff, int voff,
                             const int* __restrict__ nbr, int koff, int ppb,
                             float* __restrict__ stats, float* __restrict__ maxOut)
{
    const int c = threadIdx.x;
    const int C = blockDim.x;
    const int p0 = blockIdx.x * ppb;
    float sum = 0.f, ss = 0.f;
    for (int p = 0; p < ppb; p++) {
        int n = p0 + p;
        float un = buf[(size_t)n*stride + uoff + c];
        float vn = buf[(size_t)n*stride + voff + c];
        float w = vn - un;
        float mx = -3.4e38f;
        #pragma unroll
        for (int k = 0; k < KK; k++) {
            int j = nbr[n*11 + koff + k];
            float z = buf[(size_t)j*stride + uoff + c] + w;
            sum += z; ss += z*z;
            mx = fmaxf(mx, z);
        }
        if (maxOut) maxOut[(size_t)n*C + c] = mx;
    }
    atomicAdd(&stats[c], sum);
    atomicAdd(&stats[256 + c], ss);
}

__global__ void finalize_kernel(const float* __restrict__ stats,
                                const float* __restrict__ g, const float* __restrict__ bb,
                                int C, float cnt,
                                float* __restrict__ scale, float* __restrict__ shift)
{
    int c = blockIdx.x*blockDim.x + threadIdx.x;
    if (c >= C) return;
    float mean = stats[c] / cnt;
    float var  = stats[256 + c] / cnt - mean*mean;
    float rs = rsqrtf(var + EPS);
    float sc = g[c]*rs;
    scale[c] = sc;
    shift[c] = bb[c] - mean*sc;
}

// ---------------- f1 = relu(scale*max + shift) ----------------
__global__ void f1_kernel(const float* __restrict__ m1, const float* __restrict__ scale,
                          const float* __restrict__ shift, float* __restrict__ f1)
{
    int idx = blockIdx.x*blockDim.x + threadIdx.x;
    if (idx >= BNPTS*64) return;
    int c = idx & 63;
    f1[idx] = fmaxf(scale[c]*m1[idx] + shift[c], 0.f);
}

// ---------------- fp32 tiled GEMM with packed f32x2 accumulate ----------------
template<int BM, int BN, int TM, int TN, int NT>
__global__ __launch_bounds__(NT) void gemm_kernel(
    const float* __restrict__ A, const float* __restrict__ B, float* __restrict__ C,
    int M, int N, int Kd)
{
    __shared__ __align__(16) float As[16][BM + 4];
    __shared__ __align__(16) float Bs[16][BN];
    const int tid = threadIdx.x;
    constexpr int TX = BN / TN;
    constexpr int TNH = TN / 2;
    const int tx = tid % TX;
    const int ty = tid / TX;
    const int rowBase = blockIdx.x * BM;
    const int colBase = blockIdx.y * BN;

    unsigned long long acc[TM][TNH];
    #pragma unroll
    for (int i = 0; i < TM; i++)
        #pragma unroll
        for (int j = 0; j < TNH; j++) acc[i][j] = 0ull;

    for (int k0 = 0; k0 < Kd; k0 += 16) {
        #pragma unroll 2
        for (int i = tid; i < BM*4; i += NT) {
            int r = i >> 2, kk = (i & 3) * 4;
            const float4 v = *reinterpret_cast<const float4*>(
                &A[(size_t)(rowBase + r)*Kd + k0 + kk]);
            As[kk+0][r] = v.x; As[kk+1][r] = v.y; As[kk+2][r] = v.z; As[kk+3][r] = v.w;
        }
        #pragma unroll 2
        for (int i = tid; i < BN*4; i += NT) {
            int kk = i / (BN/4), c4 = (i % (BN/4)) * 4;
            *reinterpret_cast<float4*>(&Bs[kk][c4]) =
                *reinterpret_cast<const float4*>(&B[(size_t)(k0 + kk)*N + colBase + c4]);
        }
        __syncthreads();
        #pragma unroll
        for (int kk = 0; kk < 16; kk++) {
            unsigned long long ap[TM];
            #pragma unroll
            for (int i = 0; i < TM; i += 4) {
                float4 v = *reinterpret_cast<const float4*>(&As[kk][ty*TM + i]);
                ap[i+0] = pack2(v.x); ap[i+1] = pack2(v.y);
                ap[i+2] = pack2(v.z); ap[i+3] = pack2(v.w);
            }
            unsigned long long bp[TNH];
            #pragma unroll
            for (int j = 0; j < TNH; j += 2) {
                float4 v = *reinterpret_cast<const float4*>(&Bs[kk][tx*TN + j*2]);
                unsigned long long lo, hi;
                asm("mov.b64 %0, {%1, %2};" : "=l"(lo)
                    : "r"(__float_as_uint(v.x)), "r"(__float_as_uint(v.y)));
                asm("mov.b64 %0, {%1, %2};" : "=l"(hi)
                    : "r"(__float_as_uint(v.z)), "r"(__float_as_uint(v.w)));
                bp[j] = lo; bp[j+1] = hi;
            }
            #pragma unroll
            for (int i = 0; i < TM; i++)
                #pragma unroll
                for (int j = 0; j < TNH; j++)
                    acc[i][j] = ffma2(ap[i], bp[j], acc[i][j]);
        }
        __syncthreads();
    }
    #pragma unroll
    for (int i = 0; i < TM; i++) {
        float* cp = &C[(size_t)(rowBase + ty*TM + i)*N + colBase + tx*TN];
        #pragma unroll
        for (int j = 0; j < TNH; j += 2) {
            float4 o;
            unsigned int lx, ly, hx, hy;
            asm("mov.b64 {%0, %1}, %2;" : "=r"(lx), "=r"(ly) : "l"(acc[i][j]));
            asm("mov.b64 {%0, %1}, %2;" : "=r"(hx), "=r"(hy) : "l"(acc[i][j+1]));
            o.x = __uint_as_float(lx); o.y = __uint_as_float(ly);
            o.z = __uint_as_float(hx); o.w = __uint_as_float(hy);
            *reinterpret_cast<float4*>(cp + j*2) = o;
        }
    }
}

// ---------------- soft-edge aggregation ----------------
template<int C, int CA>
__global__ void softedge_kernel(const float* __restrict__ buf, const int* __restrict__ nbr,
                                const float* __restrict__ scale, const float* __restrict__ shift,
                                const float* __restrict__ ab,
                                const float* __restrict__ Wb, const float* __restrict__ bb,
                                float* __restrict__ fout)
{
    constexpr int STRIDE = 2*C + 2*CA;
    constexpr int AOFF = 2*C;
    const int n = blockIdx.x;
    const int t = threadIdx.x;

    __shared__ int   js[KK];
    __shared__ float wps[KK][C/32];
    __shared__ float alpha[KK];

    if (t < KK) js[t] = nbr[n*11 + 1 + t];
    __syncthreads();

    float base_a = 0.f;
    if (t < CA) {
        float usn = buf[(size_t)n*STRIDE + AOFF + t];
        base_a = buf[(size_t)n*STRIDE + AOFF + CA + t] - usn + ab[t];
    }
    #pragma unroll
    for (int k = 0; k < KK; k++) {
        float v = 0.f;
        if (t < CA) {
            float h = buf[(size_t)js[k]*STRIDE + AOFF + t] + base_a;
            h = fmaxf(h, 0.f);
            v = h * Wb[t];
        }
        #pragma unroll
        for (int off = 16; off; off >>= 1) v += __shfl_down_sync(FULLMASK, v, off);
        if ((t & 31) == 0) wps[k][t >> 5] = v;
    }
    __syncthreads();
    if (t < KK) {
        float s = 0.f;
        #pragma unroll
        for (int w = 0; w < C/32; w++) s += wps[t][w];
        alpha[t] = (s + bb[0]) / TAU;
    }
    __syncthreads();
    if (t == 0) {
        float mx = -3.4e38f;
        #pragma unroll
        for (int k = 0; k < KK; k++) mx = fmaxf(mx, alpha[k]);
        float s = 0.f;
        #pragma unroll
        for (int k = 0; k < KK; k++) { float e = expf(alpha[k] - mx); alpha[k] = e; s += e; }
        float inv = 1.f / s;
        #pragma unroll
        for (int k = 0; k < KK; k++) alpha[k] *= inv;
    }
    __syncthreads();

    float un = buf[(size_t)n*STRIDE + t];
    float w  = buf[(size_t)n*STRIDE + C + t] - un;
    float sc = scale[t], sh = shift[t];
    float acc = 0.f;
    #pragma unroll
    for (int k = 0; k < KK; k++) {
        float z = buf[(size_t)js[k]*STRIDE + t] + w;
        acc += alpha[k] * fmaxf(sc*z + sh, 0.f);
    }
    fout[(size_t)n*C + t] = acc;
}

// ---------------- final attention pooling ----------------
__global__ void wlog_kernel(const float* __restrict__ hall, const float* __restrict__ ba1,
                            const float* __restrict__ Wa2, const float* __restrict__ ba2,
                            float* __restrict__ wlog)
{
    int gw = (blockIdx.x*blockDim.x + threadIdx.x) >> 5;
    int lane = threadIdx.x & 31;
    if (gw >= BNPTS) return;
    float acc = 0.f;
    #pragma unroll
    for (int h = 0; h < 2; h++) {
        int c = lane + 32*h;
        float v = fmaxf(hall[(size_t)gw*64 + c] + ba1[c], 0.f);
        acc += v * Wa2[c];
    }
    #pragma unroll
    for (int off = 16; off; off >>= 1) acc += __shfl_down_sync(FULLMASK, acc, off);
    if (lane == 0) wlog[gw] = acc + ba2[0];
}

__global__ void batred_kernel(const float* __restrict__ wlog, float* __restrict__ bmax,
                              float* __restrict__ bsum)
{
    int b = blockIdx.x, t = threadIdx.x;
    __shared__ float red[256];
    float mx = -3.4e38f;
    for (int n = t; n < NN; n += 256) mx = fmaxf(mx, wlog[b*NN + n]);
    red[t] = mx; __syncthreads();
    for (int s = 128; s; s >>= 1) { if (t < s) red[t] = fmaxf(red[t], red[t+s]); __syncthreads(); }
    float M = red[0]; __syncthreads();
    float s = 0.f;
    for (int n = t; n < NN; n += 256) s += expf(wlog[b*NN + n] - M);
    red[t] = s; __syncthreads();
    for (int st = 128; st; st >>= 1) { if (t < st) red[t] += red[t+st]; __syncthreads(); }
    if (t == 0) { bmax[b] = M; bsum[b] = red[0]; }
}

__global__ void pool_kernel(const float* __restrict__ f3, const float* __restrict__ wlog,
                            const float* __restrict__ bmax, const float* __restrict__ bsum,
                            float* __restrict__ pooled)
{
    int b = blockIdx.y, t = threadIdx.x;
    int n0 = blockIdx.x * 256;
    __shared__ float ew[256];
    ew[t] = expf(wlog[b*NN + n0 + t] - bmax[b]) / bsum[b];
    __syncthreads();
    float acc = 0.f;
    for (int i = 0; i < 256; i++)
        acc += ew[i] * f3[((size_t)b*NN + n0 + i)*256 + t];
    atomicAdd(&pooled[b*256 + t], acc);
}

__global__ void final_kernel(const float* __restrict__ pooled, const float* __restrict__ Wfc,
                             const float* __restrict__ bfc, float* __restrict__ out)
{
    int b = blockIdx.x, t = threadIdx.x;
    __shared__ float p[256];
    p[t] = pooled[b*256 + t];
    __syncthreads();
    float acc = bfc[t];
    for (int i = 0; i < 256; i++) acc = fmaf(p[i], Wfc[i*256 + t], acc);
    out[b*256 + t] = fmaxf(acc, 0.f);
}

// ---------------- host launcher ----------------
static void* sym_addr_helper(const void* symbol)
{
    void* p = nullptr;
    cudaGetSymbolAddress(&p, symbol);
    return p;
}

extern "C" void kernel_launch(void* const* d_in, const int* in_sizes, int n_in,
                              void* d_out, int out_size)
{
    const float* x    = (const float*)d_in[0];
    const float* W1   = (const float*)d_in[1];
    const float* g1   = (const float*)d_in[2];
    const float* b1   = (const float*)d_in[3];
    const float* W2   = (const float*)d_in[4];
    const float* g2   = (const float*)d_in[5];
    const float* b2   = (const float*)d_in[6];
    const float* Ws2a = (const float*)d_in[7];
    const float* bs2a = (const float*)d_in[8];
    const float* Ws2b = (const float*)d_in[9];
    const float* bs2b = (const float*)d_in[10];
    const float* W3   = (const float*)d_in[11];
    const float* g3   = (const float*)d_in[12];
    const float* b3   = (const float*)d_in[13];
    const float* Ws3a = (const float*)d_in[14];
    const float* bs3a = (const float*)d_in[15];
    const float* Ws3b = (const float*)d_in[16];
    const float* bs3b = (const float*)d_in[17];
    const float* Wa1  = (const float*)d_in[18];
    const float* ba1  = (const float*)d_in[19];
    const float* Wa2  = (const float*)d_in[20];
    const float* ba2  = (const float*)d_in[21];
    const float* Wfc  = (const float*)d_in[22];
    const float* bfc  = (const float*)d_in[23];
    float* out = (float*)d_out;
    (void)in_sizes; (void)n_in; (void)out_size;

    int*   nbr    = (int*)  sym_addr_helper(d_nbr);
    float* buf1   = (float*)sym_addr_helper(d_buf1);
    float* m1     = (float*)sym_addr_helper(d_m1);
    float* f1     = (float*)sym_addr_helper(d_f1);
    float* buf2   = (float*)sym_addr_helper(d_buf2);
    float* f2     = (float*)sym_addr_helper(d_f2);
    float* buf3   = (float*)sym_addr_helper(d_buf3);
    float* f3     = (float*)sym_addr_helper(d_f3);
    float* hall   = (float*)sym_addr_helper(d_hall);
    float* Wc2    = (float*)sym_addr_helper(d_Wcat2);
    float* Wc3    = (float*)sym_addr_helper(d_Wcat3);
    float* stats  = (float*)sym_addr_helper(d_stats);
    float* scale  = (float*)sym_addr_helper(d_scale);
    float* shift  = (float*)sym_addr_helper(d_shift);
    float* wlog   = (float*)sym_addr_helper(d_wlog);
    float* bmax   = (float*)sym_addr_helper(d_bmax);
    float* bsum   = (float*)sym_addr_helper(d_bsum);
    float* pooled = (float*)sym_addr_helper(d_pooled);

    cudaFuncSetAttribute(knn_kernel, cudaFuncAttributeMaxDynamicSharedMemorySize, KNN_SMEM);

    // keep knn as our 4th launch so ncu recaptures it (verify the win)
    zero_all_kernel<<<14, 256>>>(stats, pooled);
    prep_kernel<<<(64*384 + 128*768 + 255)/256, 256>>>(W2, Ws2a, W3, Ws3a, Wc2, Wc3);
    uv1_kernel<<<BNPTS*64/256, 256>>>(x, W1, buf1);
    knn_kernel<<<dim3(4096/(KNN_WARPS*KNN_QB), BB), KNN_WARPS*32, KNN_SMEM>>>(x, nbr);

    // stage 1
    stats_kernel<<<BNPTS/16, 64>>>(buf1, 128, 0, 64, nbr, 0, 16, stats, m1);
    finalize_kernel<<<1, 64>>>(stats, g1, b1, 64, EDGE_COUNT, scale, shift);
    f1_kernel<<<BNPTS*64/256, 256>>>(m1, scale, shift, f1);

    // stage 2
    gemm_kernel<128,128,8,8,256><<<dim3(BNPTS/128, 3), 256>>>(f1, Wc2, buf2, BNPTS, 384, 64);
    stats_kernel<<<BNPTS/16, 128>>>(buf2, 384, 0, 128, nbr, 1, 16, stats + 512, nullptr);
    finalize_kernel<<<1, 128>>>(stats + 512, g2, b2, 128, EDGE_COUNT, scale + 256, shift + 256);
    softedge_kernel<128,64><<<BNPTS, 128>>>(buf2, nbr, scale + 256, shift + 256, bs2a, Ws2b, bs2b, f2);

    // stage 3
    gemm_kernel<128,128,8,8,256><<<dim3(BNPTS/128, 6), 256>>>(f2, Wc3, buf3, BNPTS, 768, 128);
    stats_kernel<<<BNPTS/8, 256>>>(buf3, 768, 0, 256, nbr, 1, 8, stats + 1024, nullptr);
    finalize_kernel<<<1, 256>>>(stats + 1024, g3, b3, 256, EDGE_COUNT, scale + 512, shift + 512);
    softedge_kernel<256,128><<<BNPTS, 256>>>(buf3, nbr, scale + 512, shift + 512, bs3a, Ws3b, bs3b, f3);

    // attention pooling + head
    gemm_kernel<128,64,8,4,256><<<dim3(BNPTS/128, 1), 256>>>(f3, Wa1, hall, BNPTS, 64, 256);
    wlog_kernel<<<BNPTS/8, 256>>>(hall, ba1, Wa2, ba2, wlog);
    batred_kernel<<<BB, 256>>>(wlog, bmax, bsum);
    pool_kernel<<<dim3(NN/256, BB), 256>>>(f3, wlog, bmax, bsum, pooled);
    final_kernel<<<BB, 256>>>(pooled, Wfc, bfc, out);
}

// round 6
// speedup vs baseline: 1.5989x; 1.0013x over previous
#include <cuda_runtime.h>
#include <cuda_bf16.h>
#include <cstdint>

#define BB 8
#define NN 4096
#define KK 10
#define BNPTS (BB*NN)          // 32768
#define EDGE_COUNT 327680.0f   // B*N*K
#define TAU 0.2f
#define EPS 1e-5f
#define FULLMASK 0xffffffffu

// ---------------- device scratch (no allocations allowed) ----------------
__device__ int   d_nbr[BNPTS*11];
__device__ float d_buf1[BNPTS*128];     // u1(64)|v1(64)
__device__ float d_m1[BNPTS*64];        // max_k z (stage1)
__device__ float d_f1[BNPTS*64];
__device__ float d_buf2[BNPTS*384];     // u2(128)|v2(128)|us2(64)|vs2(64)
__device__ float d_f2[BNPTS*128];
__device__ float d_buf3[BNPTS*768];     // u3(256)|v3(256)|us3(128)|vs3(128)
__device__ float d_f3[BNPTS*256];
__device__ float d_hall[BNPTS*64];
__device__ float d_Wcat2[64*384];
__device__ float d_Wcat3[128*768];
__device__ float d_stats[3*512];
__device__ float d_scale[3*256];
__device__ float d_shift[3*256];
__device__ float d_wlog[BNPTS];
__device__ float d_bmax[BB];
__device__ float d_bsum[BB];
__device__ float d_pooled[BB*256];

// ---------------- packed f32x2 fma ----------------
__device__ __forceinline__ unsigned long long ffma2(unsigned long long a,
                                                    unsigned long long b,
                                                    unsigned long long c)
{
    unsigned long long d;
    asm("fma.rn.f32x2 %0, %1, %2, %3;" : "=l"(d) : "l"(a), "l"(b), "l"(c));
    return d;
}
__device__ __forceinline__ unsigned long long pack2(float x)
{
    unsigned long long d;
    asm("mov.b64 %0, {%1, %1};" : "=l"(d) : "r"(__float_as_uint(x)));
    return d;
}

// ---------------- KNN: threshold-filter top-11, 8 queries per warp pass ----------
#define KNN_WARPS 8
#define KNN_QB 8
#define KNN_BUF 64
#define KNN_SMEM (4096*16 + KNN_WARPS*KNN_QB*KNN_BUF*8)

__device__ __forceinline__ unsigned orderable_f32(float f)
{
    unsigned u = __float_as_uint(f);
    return (u & 0x80000000u) ? ~u : (u | 0x80000000u);
}

__global__ __launch_bounds__(KNN_WARPS*32) void knn_kernel(
    const float* __restrict__ x, int* __restrict__ nbr)
{
    extern __shared__ unsigned char smem_raw[];
    float4* cand = (float4*)smem_raw;
    unsigned long long* wbuf = (unsigned long long*)(cand + 4096);

    const int b    = blockIdx.y;
    const int tid  = threadIdx.x;
    const int warp = tid >> 5;
    const int lane = tid & 31;

    for (int i = tid; i < 4096; i += blockDim.x) {
        const float* xp = x + ((size_t)b*4096 + i)*5;
        float cx = xp[0], cy = xp[1], cz = xp[2];
        cand[i] = make_float4(cx, cy, cz, cx*cx + cy*cy + cz*cz);
    }
    __syncthreads();

    const int qbase = blockIdx.x*(KNN_WARPS*KNN_QB) + warp*KNN_QB;
    unsigned long long* bufw = wbuf + (size_t)warp*KNN_QB*KNN_BUF;

    float m2x[KNN_QB], m2y[KNN_QB], m2z[KNN_QB];
    #pragma unroll
    for (int j = 0; j < KNN_QB; j++) {
        float4 Q = cand[qbase + j];
        m2x[j] = -2.f*Q.x; m2y[j] = -2.f*Q.y; m2z[j] = -2.f*Q.z;
    }

    // phase 1: per-lane minima for all queries in one scan
    float lmin[KNN_QB];
    #pragma unroll
    for (int j = 0; j < KNN_QB; j++) lmin[j] = 3.4e38f;
    for (int m = lane; m < 4096; m += 32) {
        float4 c = cand[m];
        #pragma unroll
        for (int j = 0; j < KNN_QB; j++) {
            float key = fmaf(c.x, m2x[j], fmaf(c.y, m2y[j], fmaf(c.z, m2z[j], c.w)));
            lmin[j] = fminf(lmin[j], key);
        }
    }

    // tau[j] = 11th smallest of the 32 lane minima
    float tau[KNN_QB];
    #pragma unroll
    for (int j = 0; j < KNN_QB; j++) {
        float val = lmin[j], t = 0.f;
        #pragma unroll
        for (int r = 0; r < 11; r++) {
            float mn = val;
            #pragma unroll
            for (int off = 16; off; off >>= 1)
                mn = fminf(mn, __shfl_xor_sync(FULLMASK, mn, off));
            t = mn;
            unsigned bal = __ballot_sync(FULLMASK, val == mn);
            if (lane == __ffs(bal) - 1) val = 3.4e38f;
        }
        tau[j] = t;
    }

    // phase 2: collect candidates <= tau[j]
    int cnt[KNN_QB];
    #pragma unroll
    for (int j = 0; j < KNN_QB; j++) cnt[j] = 0;
    const unsigned lt = (1u << lane) - 1u;
    for (int m = lane; m < 4096; m += 32) {
        float4 c = cand[m];
        #pragma unroll
        for (int j = 0; j < KNN_QB; j++) {
            float key = fmaf(c.x, m2x[j], fmaf(c.y, m2y[j], fmaf(c.z, m2z[j], c.w)));
            bool p = (key <= tau[j]);
            unsigned mask = __ballot_sync(FULLMASK, p);
            if (p) {
                int pos = cnt[j] + __popc(mask & lt);
                if (pos < KNN_BUF)
                    bufw[j*KNN_BUF + pos] =
                        ((unsigned long long)orderable_f32(key) << 32) | (unsigned)m;
            }
            cnt[j] += __popc(mask);
        }
    }
    __syncwarp();

    // phase 3: exact top-11 per query
    #pragma unroll
    for (int j = 0; j < KNN_QB; j++) {
        const int q = qbase + j;
        if (cnt[j] <= KNN_BUF) {
            unsigned long long v0, v1;
            v0 = (lane      < cnt[j]) ? bufw[j*KNN_BUF + lane]      : 0xffffffffffffffffull;
            v1 = (lane + 32 < cnt[j]) ? bufw[j*KNN_BUF + lane + 32] : 0xffffffffffffffffull;
            #pragma unroll
            for (int r = 0; r < 11; r++) {
                unsigned long long mn = min(v0, v1);
                #pragma unroll
                for (int off = 16; off; off >>= 1) {
                    unsigned long long o = __shfl_xor_sync(FULLMASK, mn, off);
                    if (o < mn) mn = o;
                }
                if (v0 == mn) v0 = 0xffffffffffffffffull;
                if (v1 == mn) v1 = 0xffffffffffffffffull;
                if (lane == 0)
                    nbr[((size_t)b*4096 + q)*11 + r] = b*4096 + (int)(mn & 0xffffffffu);
            }
        } else {
            unsigned long long last = 0ull;
            for (int r = 0; r < 11; r++) {
                unsigned long long lm = 0xffffffffffffffffull;
                for (int m = lane; m < 4096; m += 32) {
                    float4 c = cand[m];
                    float key = fmaf(c.x, m2x[j], fmaf(c.y, m2y[j], fmaf(c.z, m2z[j], c.w)));
                    unsigned long long pk =
                        ((unsigned long long)orderable_f32(key) << 32) | (unsigned)m;
                    if (pk > last && pk < lm) lm = pk;
                }
                unsigned long long mn = lm;
                #pragma unroll
                for (int off = 16; off; off >>= 1) {
                    unsigned long long o = __shfl_xor_sync(FULLMASK, mn, off);
                    if (o < mn) mn = o;
                }
                last = mn;
                if (lane == 0)
                    nbr[((size_t)b*4096 + q)*11 + r] = b*4096 + (int)(mn & 0xffffffffu);
            }
        }
    }
}

// ---------------- weight prep + zero accumulators (merged) ----------------
__global__ void prep_kernel(const float* __restrict__ W2, const float* __restrict__ Ws2a,
                            const float* __restrict__ W3, const float* __restrict__ Ws3a,
                            float* __restrict__ Wc2, float* __restrict__ Wc3,
                            float* __restrict__ stats, float* __restrict__ pooled)
{
    int i = blockIdx.x*blockDim.x + threadIdx.x;
    if (i < 3*512) stats[i] = 0.f;
    if (i < BB*256) pooled[i] = 0.f;
    if (i < 64*384) {
        int r = i/384, c = i%384;
        float v;
        if      (c < 128) v = W2[r*128 + c];
        else if (c < 256) v = W2[(64+r)*128 + (c-128)];
        else if (c < 320) v = Ws2a[r*64 + (c-256)];
        else              v = Ws2a[(64+r)*64 + (c-320)];
        Wc2[i] = v;
    } else {
        int j = i - 64*384;
        if (j < 128*768) {
            int r = j/768, c = j%768;
            float v;
            if      (c < 256) v = W3[r*256 + c];
            else if (c < 512) v = W3[(128+r)*256 + (c-256)];
            else if (c < 640) v = Ws3a[r*128 + (c-512)];
            else              v = Ws3a[(128+r)*128 + (c-640)];
            Wc3[j] = v;
        }
    }
}

// ---------------- stage-1 u/v ----------------
__global__ void uv1_kernel(const float* __restrict__ x, const float* __restrict__ W1,
                           float* __restrict__ buf1)
{
    int idx = blockIdx.x*blockDim.x + threadIdx.x;
    if (idx >= BNPTS*64) return;
    int n = idx >> 6, c = idx & 63;
    const float* xp = x + (size_t)n*5;
    float x0 = xp[0], x1 = xp[1], x2 = xp[2], x3 = xp[3], x4 = xp[4];
    float u = x0*W1[0*64+c] + x1*W1[1*64+c] + x2*W1[2*64+c] + x3*W1[6*64+c] + x4*W1[7*64+c];
    float v = x0*W1[3*64+c] + x1*W1[4*64+c] + x2*W1[5*64+c] + x3*W1[8*64+c] + x4*W1[9*64+c];
    buf1[n*128 + c]      = u;
    buf1[n*128 + 64 + c] = v;
}

// ---------------- BN statistics over edges ----------------
__global__ void stats_kernel(const float* __restrict__ buf, int stride, int uoff, int voff,
                             const int* __restrict__ nbr, int koff, int ppb,
                             float* __restrict__ stats, float* __restrict__ maxOut)
{
    const int c = threadIdx.x;
    const int C = blockDim.x;
    const int p0 = blockIdx.x * ppb;
    float sum = 0.f, ss = 0.f;
    for (int p = 0; p < ppb; p++) {
        int n = p0 + p;
        float un = buf[(size_t)n*stride + uoff + c];
        float vn = buf[(size_t)n*stride + voff + c];
        float w = vn - un;
        float mx = -3.4e38f;
        #pragma unroll
        for (int k = 0; k < KK; k++) {
            int j = nbr[n*11 + koff + k];
            float z = buf[(size_t)j*stride + uoff + c] + w;
            sum += z; ss += z*z;
            mx = fmaxf(mx, z);
        }
        if (maxOut) maxOut[(size_t)n*C + c] = mx;
    }
    atomicAdd(&stats[c], sum);
    atomicAdd(&stats[256 + c], ss);
}

__global__ void finalize_kernel(const float* __restrict__ stats,
                                const float* __restrict__ g, const float* __restrict__ bb,
                                int C, float cnt,
                                float* __restrict__ scale, float* __restrict__ shift)
{
    int c = blockIdx.x*blockDim.x + threadIdx.x;
    if (c >= C) return;
    float mean = stats[c] / cnt;
    float var  = stats[256 + c] / cnt - mean*mean;
    float rs = rsqrtf(var + EPS);
    float sc = g[c]*rs;
    scale[c] = sc;
    shift[c] = bb[c] - mean*sc;
}

// ---------------- f1 = relu(scale*max + shift) ----------------
__global__ void f1_kernel(const float* __restrict__ m1, const float* __restrict__ scale,
                          const float* __restrict__ shift, float* __restrict__ f1)
{
    int idx = blockIdx.x*blockDim.x + threadIdx.x;
    if (idx >= BNPTS*64) return;
    int c = idx & 63;
    f1[idx] = fmaxf(scale[c]*m1[idx] + shift[c], 0.f);
}

// ---------------- fp32 GEMM, f32x2 accumulate, double-buffered pipeline ---------
template<int BM, int BN, int TM, int TN, int NT>
__global__ __launch_bounds__(NT) void gemm_kernel(
    const float* __restrict__ A, const float* __restrict__ B, float* __restrict__ C,
    int M, int N, int Kd)
{
    __shared__ __align__(16) float As[2][16][BM + 4];
    __shared__ __align__(16) float Bs[2][16][BN];
    constexpr int A_LD = (BM*16)/(4*NT);
    constexpr int B_LD = (BN*16)/(4*NT);
    const int tid = threadIdx.x;
    constexpr int TX = BN / TN;
    constexpr int TNH = TN / 2;
    const int tx = tid % TX;
    const int ty = tid / TX;
    const int rowBase = blockIdx.x * BM;
    const int colBase = blockIdx.y * BN;

    unsigned long long acc[TM][TNH];
    #pragma unroll
    for (int i = 0; i < TM; i++)
        #pragma unroll
        for (int j = 0; j < TNH; j++) acc[i][j] = 0ull;

    float4 aReg[A_LD], bReg[B_LD];

    auto LDG = [&](int k0) {
        #pragma unroll
        for (int l = 0; l < A_LD; l++) {
            int i = tid + l*NT;
            int r = i >> 2, kk = (i & 3)*4;
            aReg[l] = *reinterpret_cast<const float4*>(
                &A[(size_t)(rowBase + r)*Kd + k0 + kk]);
        }
        #pragma unroll
        for (int l = 0; l < B_LD; l++) {
            int i = tid + l*NT;
            int kk = i/(BN/4), c4 = (i % (BN/4))*4;
            bReg[l] = *reinterpret_cast<const float4*>(
                &B[(size_t)(k0 + kk)*N + colBase + c4]);
        }
    };
    auto STS = [&](int bf) {
        #pragma unroll
        for (int l = 0; l < A_LD; l++) {
            int i = tid + l*NT;
            int r = i >> 2, kk = (i & 3)*4;
            As[bf][kk+0][r] = aReg[l].x; As[bf][kk+1][r] = aReg[l].y;
            As[bf][kk+2][r] = aReg[l].z; As[bf][kk+3][r] = aReg[l].w;
        }
        #pragma unroll
        for (int l = 0; l < B_LD; l++) {
            int i = tid + l*NT;
            int kk = i/(BN/4), c4 = (i % (BN/4))*4;
            *reinterpret_cast<float4*>(&Bs[bf][kk][c4]) = bReg[l];
        }
    };
    auto COMPUTE = [&](int bf) {
        #pragma unroll
        for (int kk = 0; kk < 16; kk++) {
            unsigned long long ap[TM];
            #pragma unroll
            for (int i = 0; i < TM; i += 4) {
                float4 v = *reinterpret_cast<const float4*>(&As[bf][kk][ty*TM + i]);
                ap[i+0] = pack2(v.x); ap[i+1] = pack2(v.y);
                ap[i+2] = pack2(v.z); ap[i+3] = pack2(v.w);
            }
            unsigned long long bp[TNH];
            #pragma unroll
            for (int j = 0; j < TNH; j += 2) {
                float4 v = *reinterpret_cast<const float4*>(&Bs[bf][kk][tx*TN + j*2]);
                unsigned long long lo, hi;
                asm("mov.b64 %0, {%1, %2};" : "=l"(lo)
                    : "r"(__float_as_uint(v.x)), "r"(__float_as_uint(v.y)));
                asm("mov.b64 %0, {%1, %2};" : "=l"(hi)
                    : "r"(__float_as_uint(v.z)), "r"(__float_as_uint(v.w)));
                bp[j] = lo; bp[j+1] = hi;
            }
            #pragma unroll
            for (int i = 0; i < TM; i++)
                #pragma unroll
                for (int j = 0; j < TNH; j++)
                    acc[i][j] = ffma2(ap[i], bp[j], acc[i][j]);
        }
    };

    const int nch = Kd / 16;
    LDG(0);
    STS(0);
    __syncthreads();
    for (int c = 0; c < nch; c++) {
        int cur = c & 1;
        if (c + 1 < nch) LDG((c + 1)*16);
        COMPUTE(cur);
        if (c + 1 < nch) STS(cur ^ 1);
        __syncthreads();
    }

    #pragma unroll
    for (int i = 0; i < TM; i++) {
        float* cp = &C[(size_t)(rowBase + ty*TM + i)*N + colBase + tx*TN];
        #pragma unroll
        for (int j = 0; j < TNH; j += 2) {
            float4 o;
            unsigned int lx, ly, hx, hy;
            asm("mov.b64 {%0, %1}, %2;" : "=r"(lx), "=r"(ly) : "l"(acc[i][j]));
            asm("mov.b64 {%0, %1}, %2;" : "=r"(hx), "=r"(hy) : "l"(acc[i][j+1]));
            o.x = __uint_as_float(lx); o.y = __uint_as_float(ly);
            o.z = __uint_as_float(hx); o.w = __uint_as_float(hy);
            *reinterpret_cast<float4*>(cp + j*2) = o;
        }
    }
}

// ---------------- soft-edge aggregation ----------------
template<int C, int CA>
__global__ void softedge_kernel(const float* __restrict__ buf, const int* __restrict__ nbr,
                                const float* __restrict__ scale, const float* __restrict__ shift,
                                const float* __restrict__ ab,
                                const float* __restrict__ Wb, const float* __restrict__ bb,
                                float* __restrict__ fout)
{
    constexpr int STRIDE = 2*C + 2*CA;
    constexpr int AOFF = 2*C;
    const int n = blockIdx.x;
    const int t = threadIdx.x;

    __shared__ int   js[KK];
    __shared__ float wps[KK][C/32];
    __shared__ float alpha[KK];

    if (t < KK) js[t] = nbr[n*11 + 1 + t];
    __syncthreads();

    float base_a = 0.f;
    if (t < CA) {
        float usn = buf[(size_t)n*STRIDE + AOFF + t];
        base_a = buf[(size_t)n*STRIDE + AOFF + CA + t] - usn + ab[t];
    }
    #pragma unroll
    for (int k = 0; k < KK; k++) {
        float v = 0.f;
        if (t < CA) {
            float h = buf[(size_t)js[k]*STRIDE + AOFF + t] + base_a;
            h = fmaxf(h, 0.f);
            v = h * Wb[t];
        }
        #pragma unroll
        for (int off = 16; off; off >>= 1) v += __shfl_down_sync(FULLMASK, v, off);
        if ((t & 31) == 0) wps[k][t >> 5] = v;
    }
    __syncthreads();
    if (t < KK) {
        float s = 0.f;
        #pragma unroll
        for (int w = 0; w < C/32; w++) s += wps[t][w];
        alpha[t] = (s + bb[0]) / TAU;
    }
    __syncthreads();
    if (t == 0) {
        float mx = -3.4e38f;
        #pragma unroll
        for (int k = 0; k < KK; k++) mx = fmaxf(mx, alpha[k]);
        float s = 0.f;
        #pragma unroll
        for (int k = 0; k < KK; k++) { float e = expf(alpha[k] - mx); alpha[k] = e; s += e; }
        float inv = 1.f / s;
        #pragma unroll
        for (int k = 0; k < KK; k++) alpha[k] *= inv;
    }
    __syncthreads();

    float un = buf[(size_t)n*STRIDE + t];
    float w  = buf[(size_t)n*STRIDE + C + t] - un;
    float sc = scale[t], sh = shift[t];
    float acc = 0.f;
    #pragma unroll
    for (int k = 0; k < KK; k++) {
        float z = buf[(size_t)js[k]*STRIDE + t] + w;
        acc += alpha[k] * fmaxf(sc*z + sh, 0.f);
    }
    fout[(size_t)n*C + t] = acc;
}

// ---------------- final attention pooling ----------------
__global__ void wlog_kernel(const float* __restrict__ hall, const float* __restrict__ ba1,
                            const float* __restrict__ Wa2, const float* __restrict__ ba2,
                            float* __restrict__ wlog)
{
    int gw = (blockIdx.x*blockDim.x + threadIdx.x) >> 5;
    int lane = threadIdx.x & 31;
    if (gw >= BNPTS) return;
    float acc = 0.f;
    #pragma unroll
    for (int h = 0; h < 2; h++) {
        int c = lane + 32*h;
        float v = fmaxf(hall[(size_t)gw*64 + c] + ba1[c], 0.f);
        acc += v * Wa2[c];
    }
    #pragma unroll
    for (int off = 16; off; off >>= 1) acc += __shfl_down_sync(FULLMASK, acc, off);
    if (lane == 0) wlog[gw] = acc + ba2[0];
}

__global__ void batred_kernel(const float* __restrict__ wlog, float* __restrict__ bmax,
                              float* __restrict__ bsum)
{
    int b = blockIdx.x, t = threadIdx.x;
    __shared__ float red[256];
    float mx = -3.4e38f;
    for (int n = t; n < NN; n += 256) mx = fmaxf(mx, wlog[b*NN + n]);
    red[t] = mx; __syncthreads();
    for (int s = 128; s; s >>= 1) { if (t < s) red[t] = fmaxf(red[t], red[t+s]); __syncthreads(); }
    float M = red[0]; __syncthreads();
    float s = 0.f;
    for (int n = t; n < NN; n += 256) s += expf(wlog[b*NN + n] - M);
    red[t] = s; __syncthreads();
    for (int st = 128; st; st >>= 1) { if (t < st) red[t] += red[t+st]; __syncthreads(); }
    if (t == 0) { bmax[b] = M; bsum[b] = red[0]; }
}

__global__ void pool_kernel(const float* __restrict__ f3, const float* __restrict__ wlog,
                            const float* __restrict__ bmax, const float* __restrict__ bsum,
                            float* __restrict__ pooled)
{
    int b = blockIdx.y, t = threadIdx.x;
    int n0 = blockIdx.x * 256;
    __shared__ float ew[256];
    ew[t] = expf(wlog[b*NN + n0 + t] - bmax[b]) / bsum[b];
    __syncthreads();
    float acc = 0.f;
    for (int i = 0; i < 256; i++)
        acc += ew[i] * f3[((size_t)b*NN + n0 + i)*256 + t];
    atomicAdd(&pooled[b*256 + t], acc);
}

__global__ void final_kernel(const float* __restrict__ pooled, const float* __restrict__ Wfc,
                             const float* __restrict__ bfc, float* __restrict__ out)
{
    int b = blockIdx.x, t = threadIdx.x;
    __shared__ float p[256];
    p[t] = pooled[b*256 + t];
    __syncthreads();
    float acc = bfc[t];
    for (int i = 0; i < 256; i++) acc = fmaf(p[i], Wfc[i*256 + t], acc);
    out[b*256 + t] = fmaxf(acc, 0.f);
}

// ---------------- host launcher ----------------
static void* sym_addr_helper(const void* symbol)
{
    void* p = nullptr;
    cudaGetSymbolAddress(&p, symbol);
    return p;
}

extern "C" void kernel_launch(void* const* d_in, const int* in_sizes, int n_in,
                              void* d_out, int out_size)
{
    const float* x    = (const float*)d_in[0];
    const float* W1   = (const float*)d_in[1];
    const float* g1   = (const float*)d_in[2];
    const float* b1   = (const float*)d_in[3];
    const float* W2   = (const float*)d_in[4];
    const float* g2   = (const float*)d_in[5];
    const float* b2   = (const float*)d_in[6];
    const float* Ws2a = (const float*)d_in[7];
    const float* bs2a = (const float*)d_in[8];
    const float* Ws2b = (const float*)d_in[9];
    const float* bs2b = (const float*)d_in[10];
    const float* W3   = (const float*)d_in[11];
    const float* g3   = (const float*)d_in[12];
    const float* b3   = (const float*)d_in[13];
    const float* Ws3a = (const float*)d_in[14];
    const float* bs3a = (const float*)d_in[15];
    const float* Ws3b = (const float*)d_in[16];
    const float* bs3b = (const float*)d_in[17];
    const float* Wa1  = (const float*)d_in[18];
    const float* ba1  = (const float*)d_in[19];
    const float* Wa2  = (const float*)d_in[20];
    const float* ba2  = (const float*)d_in[21];
    const float* Wfc  = (const float*)d_in[22];
    const float* bfc  = (const float*)d_in[23];
    float* out = (float*)d_out;
    (void)in_sizes; (void)n_in; (void)out_size;

    int*   nbr    = (int*)  sym_addr_helper(d_nbr);
    float* buf1   = (float*)sym_addr_helper(d_buf1);
    float* m1     = (float*)sym_addr_helper(d_m1);
    float* f1     = (float*)sym_addr_helper(d_f1);
    float* buf2   = (float*)sym_addr_helper(d_buf2);
    float* f2     = (float*)sym_addr_helper(d_f2);
    float* buf3   = (float*)sym_addr_helper(d_buf3);
    float* f3     = (float*)sym_addr_helper(d_f3);
    float* hall   = (float*)sym_addr_helper(d_hall);
    float* Wc2    = (float*)sym_addr_helper(d_Wcat2);
    float* Wc3    = (float*)sym_addr_helper(d_Wcat3);
    float* stats  = (float*)sym_addr_helper(d_stats);
    float* scale  = (float*)sym_addr_helper(d_scale);
    float* shift  = (float*)sym_addr_helper(d_shift);
    float* wlog   = (float*)sym_addr_helper(d_wlog);
    float* bmax   = (float*)sym_addr_helper(d_bmax);
    float* bsum   = (float*)sym_addr_helper(d_bsum);
    float* pooled = (float*)sym_addr_helper(d_pooled);

    cudaFuncSetAttribute(knn_kernel, cudaFuncAttributeMaxDynamicSharedMemorySize, KNN_SMEM);

    // launch order: prep(1), uv1(2), knn(3), stats1(4) <- ncu -s 5 capture window
    prep_kernel<<<(64*384 + 128*768 + 255)/256, 256>>>(W2, Ws2a, W3, Ws3a, Wc2, Wc3,
                                                        stats, pooled);
    uv1_kernel<<<BNPTS*64/256, 256>>>(x, W1, buf1);
    knn_kernel<<<dim3(4096/(KNN_WARPS*KNN_QB), BB), KNN_WARPS*32, KNN_SMEM>>>(x, nbr);

    // stage 1
    stats_kernel<<<BNPTS/16, 64>>>(buf1, 128, 0, 64, nbr, 0, 16, stats, m1);
    finalize_kernel<<<1, 64>>>(stats, g1, b1, 64, EDGE_COUNT, scale, shift);
    f1_kernel<<<BNPTS*64/256, 256>>>(m1, scale, shift, f1);

    // stage 2
    gemm_kernel<128,128,8,8,256><<<dim3(BNPTS/128, 3), 256>>>(f1, Wc2, buf2, BNPTS, 384, 64);
    stats_kernel<<<BNPTS/16, 128>>>(buf2, 384, 0, 128, nbr, 1, 16, stats + 512, nullptr);
    finalize_kernel<<<1, 128>>>(stats + 512, g2, b2, 128, EDGE_COUNT, scale + 256, shift + 256);
    softedge_kernel<128,64><<<BNPTS, 128>>>(buf2, nbr, scale + 256, shift + 256, bs2a, Ws2b, bs2b, f2);

    // stage 3
    gemm_kernel<128,128,8,8,256><<<dim3(BNPTS/128, 6), 256>>>(f2, Wc3, buf3, BNPTS, 768, 128);
    stats_kernel<<<BNPTS/8, 256>>>(buf3, 768, 0, 256, nbr, 1, 8, stats + 1024, nullptr);
    finalize_kernel<<<1, 256>>>(stats + 1024, g3, b3, 256, EDGE_COUNT, scale + 512, shift + 512);
    softedge_kernel<256,128><<<BNPTS, 256>>>(buf3, nbr, scale + 512, shift + 512, bs3a, Ws3b, bs3b, f3);

    // attention pooling + head
    gemm_kernel<128,64,8,4,256><<<dim3(BNPTS/128, 1), 256>>>(f3, Wa1, hall, BNPTS, 64, 256);
    wlog_kernel<<<BNPTS/8, 256>>>(hall, ba1, Wa2, ba2, wlog);
    batred_kernel<<<BB, 256>>>(wlog, bmax, bsum);
    pool_kernel<<<dim3(NN/256, BB), 256>>>(f3, wlog, bmax, bsum, pooled);
    final_kernel<<<BB, 256>>>(pooled, Wfc, bfc, out);
}